// round 2
// baseline (speedup 1.0000x reference)
#include <cuda_runtime.h>
#include <math.h>

// Problem constants
#define NB    64      // batch
#define NSEQ  64      // seq (after dropping last obs)
#define NIMG  4096    // NB*NSEQ
#define HW    49      // 7*7
#define NC    128     // channels
#define NS    8       // S
#define NK    512     // K
#define NE    64      // E

// ---------------- device scratch (no allocations allowed) ----------------
__device__ float g_X0[NIMG*HW*NC];     // ~98MB
__device__ float g_X1[NIMG*HW*NC];     // ~98MB
__device__ float g_obs_feat[NIMG*NC];  // (b*64+t)*128+c
__device__ float g_bn_sum[NC];
__device__ float g_bn_sumsq[NC];
__device__ float g_h[NB*64];
__device__ float g_z[NB*512];
__device__ int   g_idxs[NB*NS];
__device__ float g_zq[NB*512];
__device__ float g_gamma[NB*128];
__device__ float g_beta[NB*128];
__device__ float g_cb[NS*NK*NE];
__device__ float g_cs[NS*NK];
__device__ float g_ea[NS*NK*NE];
__device__ float g_counts[NK];
__device__ float g_sums[NK*NE];
__device__ double g_decl;
__device__ double g_el;

// ---------------- init ----------------
__global__ void k_init(const float* __restrict__ codebook) {
    int i = blockIdx.x * blockDim.x + threadIdx.x;  // 512*512 = 262144 threads
    if (i < NS*NK*NE) { g_cb[i] = codebook[i]; g_ea[i] = codebook[i]; }
    if (i < NS*NK)    { g_cs[i] = 0.f; }
    if (i < NB*64)    { g_h[i] = 0.f; }
    if (i == 0)       { g_decl = 0.0; g_el = 0.0; }
}

// ---------------- embedding gather + sum over 3 planes ----------------
__global__ void k_embed(const int* __restrict__ obs, const float* __restrict__ emb) {
    int n = blockIdx.x;            // 0..4095 : b*64 + t
    int b = n >> 6, t = n & 63;
    int c = threadIdx.x;           // 128
    __shared__ int sidx[3*HW];
    for (int j = c; j < 3*HW; j += 128) {
        int i = j / HW, pos = j % HW;
        sidx[j] = obs[(((b*65 + t)*3 + i)*HW) + pos] + i * 147;
    }
    __syncthreads();
    float* outp = g_X0 + (size_t)n * HW * NC;
    for (int pos = 0; pos < HW; pos++) {
        float v = emb[sidx[pos]*NC + c]
                + emb[sidx[HW + pos]*NC + c]
                + emb[sidx[2*HW + pos]*NC + c];
        outp[pos*NC + c] = v;
    }
}

// ---------------- 3x3 SAME conv, NHWC, 128->128 ----------------
// One block per image; thread = output channel; 49 accumulators in registers,
// 9x9x128 zero-padded input patch in smem. 441 FMAs per 9 weight loads.
template<int DIR>
__global__ __launch_bounds__(128) void k_conv(const float* __restrict__ w,
                                              const float* __restrict__ bias) {
    const float* in = (DIR == 0) ? g_X0 : g_X1;
    float*      out = (DIR == 0) ? g_X1 : g_X0;
    __shared__ float P[81*NC];   // 9x9 padded, 41472 bytes
    int n  = blockIdx.x;
    int co = threadIdx.x;
    for (int i = co; i < 81*NC; i += 128) P[i] = 0.f;
    __syncthreads();
    const float* inp = in + (size_t)n * HW * NC;
    for (int i = co; i < HW*NC; i += 128) {
        int pos = i >> 7, ci = i & 127;
        int h = pos / 7, wv = pos % 7;
        P[((h+1)*9 + (wv+1))*NC + ci] = inp[i];
    }
    __syncthreads();
    float acc[49];
    float bv = bias[co];
    #pragma unroll
    for (int p = 0; p < 49; p++) acc[p] = bv;
    for (int ci = 0; ci < NC; ci++) {
        float iv[81];
        #pragma unroll
        for (int q = 0; q < 81; q++) iv[q] = P[q*NC + ci];
        #pragma unroll
        for (int kh = 0; kh < 3; kh++) {
            #pragma unroll
            for (int kw = 0; kw < 3; kw++) {
                float wv = w[((kh*3 + kw)*NC + ci)*NC + co];
                #pragma unroll
                for (int p = 0; p < 49; p++) {
                    int oh = p / 7, ow = p % 7;
                    acc[p] += iv[(oh+kh)*9 + (ow+kw)] * wv;
                }
            }
        }
    }
    float* op = out + (size_t)n * HW * NC;
    #pragma unroll
    for (int p = 0; p < 49; p++) op[p*NC + co] = acc[p];
    if (n == 0) { g_bn_sum[co] = 0.f; g_bn_sumsq[co] = 0.f; }  // reset for next stat pass
}

// ---------------- batchnorm stats (sum, sumsq per channel) ----------------
template<int WHICH>
__global__ void k_bnstat() {
    const float* x = (WHICH == 0) ? g_X1 : g_X0;
    int n = blockIdx.x, c = threadIdx.x;
    const float* p = x + (size_t)n * HW * NC;
    float s = 0.f, s2 = 0.f;
    for (int i = 0; i < HW; i++) { float v = p[i*NC + c]; s += v; s2 += v*v; }
    atomicAdd(&g_bn_sum[c], s);
    atomicAdd(&g_bn_sumsq[c], s2);
}

// ---------------- batchnorm apply + relu (in place) ----------------
template<int WHICH>
__global__ void k_bnapply(const float* __restrict__ g, const float* __restrict__ bb) {
    float* x = (WHICH == 0) ? g_X1 : g_X0;
    int i = blockIdx.x * blockDim.x + threadIdx.x;
    if (i >= NIMG*HW*NC) return;
    int c = i & 127;
    const float invN = 1.f / (float)(NIMG*HW);
    float m = g_bn_sum[c] * invN;
    float v = g_bn_sumsq[c] * invN - m*m;
    float sc = g[c] / sqrtf(v + 1e-5f);
    float val = (x[i] - m) * sc + bb[c];
    x[i] = fmaxf(val, 0.f);
}

// ---------------- max over HW then relu -> obs_feat ----------------
__global__ void k_maxpool() {
    int n = blockIdx.x, c = threadIdx.x;
    const float* p = g_X0 + (size_t)n * HW * NC;   // conv2 path output lives in X0
    float m = p[c];
    for (int i = 1; i < HW; i++) m = fmaxf(m, p[i*NC + c]);
    g_obs_feat[n*NC + c] = fmaxf(m, 0.f);
}

// ---------------- GRU step + z projection (+ zero VQ stats) ----------------
__global__ void k_gru(int t,
                      const float* __restrict__ wih, const float* __restrict__ whh,
                      const float* __restrict__ bih, const float* __restrict__ bhh,
                      const float* __restrict__ prew, const float* __restrict__ preb) {
    int b = blockIdx.x;        // 64
    int tid = threadIdx.x;     // 512
    if (b == 0) g_counts[tid] = 0.f;
    g_sums[b*512 + tid] = 0.f;  // 64*512 == 512*64 total elements
    __shared__ float xs[128], hs[64], gi[192], gh[192], hn_[64];
    if (tid < 128) xs[tid] = g_obs_feat[(b*64 + t)*NC + tid];
    if (tid < 64)  hs[tid] = g_h[b*64 + tid];
    __syncthreads();
    if (tid < 192) {
        float a = bih[tid];
        for (int i = 0; i < 128; i++) a += xs[i] * wih[tid*128 + i];
        gi[tid] = a;
        float bbv = bhh[tid];
        for (int i = 0; i < 64; i++) bbv += hs[i] * whh[tid*64 + i];
        gh[tid] = bbv;
    }
    __syncthreads();
    if (tid < 64) {
        float r  = 1.f / (1.f + expf(-(gi[tid]       + gh[tid])));
        float zz = 1.f / (1.f + expf(-(gi[64 + tid]  + gh[64 + tid])));
        float nn = tanhf(gi[128 + tid] + r * gh[128 + tid]);
        float h  = (1.f - zz) * nn + zz * hs[tid];
        hn_[tid] = h;
        g_h[b*64 + tid] = h;
    }
    __syncthreads();
    float a = preb[tid];
    for (int i = 0; i < 64; i++) a += hn_[i] * prew[i*512 + tid];
    g_z[b*512 + tid] = a;
}

// ---------------- VQ argmin + gather z_q (old cb) + stats + e_l ----------------
__global__ void k_vq() {
    int bs = blockIdx.x;           // 512 blocks = b*8 + s
    int b = bs >> 3, s = bs & 7;
    int tid = threadIdx.x;         // 256
    __shared__ float zs[64];
    __shared__ float bd[256];
    __shared__ int   bi[256];
    if (tid < 64) zs[tid] = g_z[b*512 + s*64 + tid];
    __syncthreads();
    const float* cbp = g_cb + (size_t)s * NK * NE;
    float best = 3.4e38f; int bk = 0;
    for (int k = tid; k < NK; k += 256) {
        const float* row = cbp + k*64;
        float d = 0.f;
        #pragma unroll
        for (int e = 0; e < 64; e++) { float df = zs[e] - row[e]; d += df*df; }
        if (d < best) { best = d; bk = k; }   // k ascending per-thread => first-min
    }
    bd[tid] = best; bi[tid] = bk;
    __syncthreads();
    for (int off = 128; off > 0; off >>= 1) {
        if (tid < off) {
            float d2 = bd[tid + off]; int k2 = bi[tid + off];
            if (d2 < bd[tid] || (d2 == bd[tid] && k2 < bi[tid])) { bd[tid] = d2; bi[tid] = k2; }
        }
        __syncthreads();
    }
    int kmin = bi[0];
    if (tid == 0) {
        g_idxs[b*NS + s] = kmin;
        atomicAdd(&g_counts[kmin], 1.0f);
        atomicAdd(&g_el, (double)bd[0] * (1.0 / 32768.0));  // /(B*S*E)
    }
    if (tid < 64) {
        g_zq[b*512 + s*64 + tid] = cbp[kmin*64 + tid];       // old-cb gather
        atomicAdd(&g_sums[kmin*64 + tid], zs[tid]);
    }
}

// ---------------- EMA codebook update (broadcast over S, as in reference) ---
__global__ void k_cbup() {
    int s = blockIdx.x;         // 8
    int k = threadIdx.x;        // 512
    __shared__ float red[512];
    float cs = g_cs[s*NK + k] * 0.99f + 0.01f * g_counts[k];
    g_cs[s*NK + k] = cs;
    red[k] = cs;
    __syncthreads();
    for (int off = 256; off > 0; off >>= 1) { if (k < off) red[k] += red[k + off]; __syncthreads(); }
    float ntot = red[0];
    float csn = (cs + 1e-5f) / (ntot + 512.f * 1e-5f) * ntot;
    size_t base = ((size_t)s*NK + k) * NE;
    for (int e = 0; e < NE; e++) {
        float ea = g_ea[base + e] * 0.99f + 0.01f * g_sums[k*NE + e];
        g_ea[base + e] = ea;
        g_cb[base + e] = ea / csn;
    }
}

// ---------------- FiLM MLP: zq -> relu(512->128) -> 128->256 -> gamma/beta --
__global__ void k_mlp(const float* __restrict__ m1w, const float* __restrict__ m1b,
                      const float* __restrict__ m2w, const float* __restrict__ m2b) {
    int b = blockIdx.x, tid = threadIdx.x;   // 64 blocks, 256 threads
    __shared__ float zq[512], h1[128];
    for (int j = tid; j < 512; j += 256) zq[j] = g_zq[b*512 + j];
    __syncthreads();
    if (tid < 128) {
        float a = m1b[tid];
        for (int i = 0; i < 512; i++) a += zq[i] * m1w[i*128 + tid];
        h1[tid] = fmaxf(a, 0.f);
    }
    __syncthreads();
    float a = m2b[tid];
    for (int i = 0; i < 128; i++) a += h1[i] * m2w[i*256 + tid];
    if (tid < 128) g_gamma[b*128 + tid] = 1.f + a;
    else           g_beta[b*128 + (tid - 128)] = a;
}

// ---------------- decoder over rows p=t..62, 8 rows per block ----------------
__global__ __launch_bounds__(128) void k_dec(int t, const int* __restrict__ acts,
        const float* __restrict__ w1, const float* __restrict__ b1,
        const float* __restrict__ w2, const float* __restrict__ b2,
        const float* __restrict__ w3, const float* __restrict__ b3) {
    int base = blockIdx.x * 8;          // rows = (63-t)*64, always multiple of 8
    int c = threadIdx.x;                // 128
    __shared__ float f[8][128];
    __shared__ float h1[8][128];
    __shared__ float h2[8][128];
    __shared__ float lg[8][6];
    __shared__ float ce[8];
    #pragma unroll
    for (int j = 0; j < 8; j++) {
        int rr = base + j;
        int p = t + (rr >> 6), b = rr & 63;
        float of = g_obs_feat[(b*64 + p)*NC + c];
        float fl = of * g_gamma[b*128 + c] + g_beta[b*128 + c];
        f[j][c] = fmaxf(fl, 0.f);       // relu(film)
    }
    __syncthreads();
    float acc[8];
    float bv = b1[c];
    #pragma unroll
    for (int j = 0; j < 8; j++) acc[j] = bv;
    for (int i = 0; i < 128; i++) {
        float wv = w1[i*128 + c];
        #pragma unroll
        for (int j = 0; j < 8; j++) acc[j] += f[j][i] * wv;
    }
    #pragma unroll
    for (int j = 0; j < 8; j++) h1[j][c] = fmaxf(acc[j], 0.f);
    __syncthreads();
    bv = b2[c];
    #pragma unroll
    for (int j = 0; j < 8; j++) acc[j] = bv;
    for (int i = 0; i < 128; i++) {
        float wv = w2[i*128 + c];
        #pragma unroll
        for (int j = 0; j < 8; j++) acc[j] += h1[j][i] * wv;
    }
    #pragma unroll
    for (int j = 0; j < 8; j++) h2[j][c] = fmaxf(acc[j], 0.f);
    __syncthreads();
    if (c < 48) {
        int j = c / 6, o = c % 6;
        float l = b3[o];
        for (int i = 0; i < 128; i++) l += h2[j][i] * w3[i*6 + o];
        lg[j][o] = l;
    }
    __syncthreads();
    if (c < 8) {
        int rr = base + c;
        int p = t + (rr >> 6), b = rr & 63;
        float m = lg[c][0];
        #pragma unroll
        for (int i = 1; i < 6; i++) m = fmaxf(m, lg[c][i]);
        float se = 0.f;
        #pragma unroll
        for (int i = 0; i < 6; i++) se += expf(lg[c][i] - m);
        float lse = m + logf(se);
        int a = acts[b*63 + p];          // p <= 62 always
        ce[c] = lse - lg[c][a];
    }
    __syncthreads();
    if (c == 0) {
        double ssum = 0.0;
        #pragma unroll
        for (int j = 0; j < 8; j++) ssum += (double)ce[j];
        atomicAdd(&g_decl, ssum);
    }
}

// ---------------- finalize ----------------
__global__ void k_final(float* __restrict__ out) {
    if (threadIdx.x == 0) {
        out[0] = (float)(g_decl / 64.0);
        out[1] = (float)(g_el / 64.0);
    }
}

// ---------------- launch ----------------
extern "C" void kernel_launch(void* const* d_in, const int* in_sizes, int n_in,
                              void* d_out, int out_size) {
    const int*   obs  = (const int*)d_in[0];
    const int*   acts = (const int*)d_in[1];
    const float* emb  = (const float*)d_in[2];
    const float* c1w  = (const float*)d_in[3];
    const float* c1b  = (const float*)d_in[4];
    const float* bn1g = (const float*)d_in[5];
    const float* bn1b = (const float*)d_in[6];
    const float* c2w  = (const float*)d_in[7];
    const float* c2b  = (const float*)d_in[8];
    const float* bn2g = (const float*)d_in[9];
    const float* bn2b = (const float*)d_in[10];
    const float* wih  = (const float*)d_in[11];
    const float* whh  = (const float*)d_in[12];
    const float* bih  = (const float*)d_in[13];
    const float* bhh  = (const float*)d_in[14];
    const float* prew = (const float*)d_in[15];
    const float* preb = (const float*)d_in[16];
    const float* cbk  = (const float*)d_in[17];
    const float* m1w  = (const float*)d_in[18];
    const float* m1b  = (const float*)d_in[19];
    const float* m2w  = (const float*)d_in[20];
    const float* m2b  = (const float*)d_in[21];
    const float* d1w  = (const float*)d_in[22];
    const float* d1b  = (const float*)d_in[23];
    const float* d2w  = (const float*)d_in[24];
    const float* d2b  = (const float*)d_in[25];
    const float* d3w  = (const float*)d_in[26];
    const float* d3b  = (const float*)d_in[27];
    float* out = (float*)d_out;

    k_init<<<512, 512>>>(cbk);
    k_embed<<<NIMG, 128>>>(obs, emb);
    k_conv<0><<<NIMG, 128>>>(c1w, c1b);
    k_bnstat<0><<<NIMG, 128>>>();
    k_bnapply<0><<<(NIMG*HW*NC + 255) / 256, 256>>>(bn1g, bn1b);
    k_conv<1><<<NIMG, 128>>>(c2w, c2b);
    k_bnstat<1><<<NIMG, 128>>>();
    k_bnapply<1><<<(NIMG*HW*NC + 255) / 256, 256>>>(bn2g, bn2b);
    k_maxpool<<<NIMG, 128>>>();

    for (int t = 0; t < 63; t++) {
        k_gru<<<NB, 512>>>(t, wih, whh, bih, bhh, prew, preb);
        k_vq<<<NB*NS, 256>>>();
        k_cbup<<<NS, 512>>>();
        k_mlp<<<NB, 256>>>(m1w, m1b, m2w, m2b);
        int rows = (63 - t) * 64;
        k_dec<<<rows / 8, 128>>>(t, acts, d1w, d1b, d2w, d2b, d3w, d3b);
    }
    k_final<<<1, 32>>>(out);
}

// round 3
// speedup vs baseline: 3.0178x; 3.0178x over previous
#include <cuda_runtime.h>
#include <math.h>

// Problem constants
#define NB    64      // batch
#define NSEQ  64      // seq (after dropping last obs)
#define NIMG  4096    // NB*NSEQ
#define HW    49      // 7*7
#define NC    128     // channels
#define NS    8       // S
#define NK    512     // K
#define NE    64      // E
#define NT    63      // scan steps

// ---------------- device scratch (no allocations allowed) ----------------
__device__ float g_X0[NIMG*HW*NC];     // ~98MB
__device__ float g_X1[NIMG*HW*NC];     // ~98MB
__device__ float g_obs_feat[NIMG*NC];
__device__ float g_gi[NIMG*192];       // precomputed x@Wih^T + bih
__device__ float g_bn_sum[NC];
__device__ float g_bn_sumsq[NC];
__device__ float g_h[NB*64];
__device__ float g_z[NB*512];
__device__ float g_cb[NS*NK*NE];
__device__ float g_csA[NS*NK];
__device__ float g_csB[NS*NK];
__device__ float g_ea[NS*NK*NE];
__device__ float g_counts[NK];
__device__ float g_sums[NK*NE];
__device__ float g_pd[64*64];          // partial argmin dist  [(s*8+kc)][b]
__device__ int   g_pi[64*64];          // partial argmin index (k within s)
__device__ float g_gab_g[NT*NB*NC];    // gamma per step
__device__ float g_gab_b[NT*NB*NC];    // beta  per step
__device__ double g_decl;
__device__ double g_el;

// ---------------- init ----------------
__global__ void k_init(const float* __restrict__ codebook) {
    int i = blockIdx.x * blockDim.x + threadIdx.x;
    if (i < NS*NK*NE) { g_cb[i] = codebook[i]; g_ea[i] = codebook[i]; }
    if (i < NS*NK)    { g_csA[i] = 0.f; g_csB[i] = 0.f; }
    if (i < NB*64)    { g_h[i] = 0.f; }
    if (i == 0)       { g_decl = 0.0; g_el = 0.0; }
}

// ---------------- embedding gather + sum over 3 planes ----------------
__global__ void k_embed(const int* __restrict__ obs, const float* __restrict__ emb) {
    int n = blockIdx.x;            // 0..4095 : b*64 + t
    int b = n >> 6, t = n & 63;
    int c = threadIdx.x;           // 128
    __shared__ int sidx[3*HW];
    for (int j = c; j < 3*HW; j += 128) {
        int i = j / HW, pos = j % HW;
        sidx[j] = obs[(((b*65 + t)*3 + i)*HW) + pos] + i * 147;
    }
    __syncthreads();
    float* outp = g_X0 + (size_t)n * HW * NC;
    for (int pos = 0; pos < HW; pos++) {
        float v = emb[sidx[pos]*NC + c]
                + emb[sidx[HW + pos]*NC + c]
                + emb[sidx[2*HW + pos]*NC + c];
        outp[pos*NC + c] = v;
    }
}

// ---------------- 3x3 SAME conv, NHWC, 128->128 ----------------
template<int DIR>
__global__ __launch_bounds__(128) void k_conv(const float* __restrict__ w,
                                              const float* __restrict__ bias) {
    const float* in = (DIR == 0) ? g_X0 : g_X1;
    float*      out = (DIR == 0) ? g_X1 : g_X0;
    __shared__ float P[81*NC];   // 9x9 padded
    int n  = blockIdx.x;
    int co = threadIdx.x;
    for (int i = co; i < 81*NC; i += 128) P[i] = 0.f;
    __syncthreads();
    const float* inp = in + (size_t)n * HW * NC;
    for (int i = co; i < HW*NC; i += 128) {
        int pos = i >> 7, ci = i & 127;
        int h = pos / 7, wv = pos % 7;
        P[((h+1)*9 + (wv+1))*NC + ci] = inp[i];
    }
    __syncthreads();
    float acc[49];
    float bv = bias[co];
    #pragma unroll
    for (int p = 0; p < 49; p++) acc[p] = bv;
    for (int ci = 0; ci < NC; ci++) {
        float iv[81];
        #pragma unroll
        for (int q = 0; q < 81; q++) iv[q] = P[q*NC + ci];
        #pragma unroll
        for (int kh = 0; kh < 3; kh++) {
            #pragma unroll
            for (int kw = 0; kw < 3; kw++) {
                float wv = w[((kh*3 + kw)*NC + ci)*NC + co];
                #pragma unroll
                for (int p = 0; p < 49; p++) {
                    int oh = p / 7, ow = p % 7;
                    acc[p] += iv[(oh+kh)*9 + (ow+kw)] * wv;
                }
            }
        }
    }
    float* op = out + (size_t)n * HW * NC;
    #pragma unroll
    for (int p = 0; p < 49; p++) op[p*NC + co] = acc[p];
    if (n == 0) { g_bn_sum[co] = 0.f; g_bn_sumsq[co] = 0.f; }
}

// ---------------- batchnorm stats (16 images per block) ----------------
template<int WHICH>
__global__ void k_bnstat() {
    const float* x = (WHICH == 0) ? g_X1 : g_X0;
    int c = threadIdx.x;
    int n0 = blockIdx.x * 16;
    float s = 0.f, s2 = 0.f;
    for (int img = 0; img < 16; img++) {
        const float* p = x + (size_t)(n0 + img) * HW * NC;
        #pragma unroll 7
        for (int i = 0; i < HW; i++) { float v = p[i*NC + c]; s += v; s2 += v*v; }
    }
    atomicAdd(&g_bn_sum[c], s);
    atomicAdd(&g_bn_sumsq[c], s2);
}

// ---------------- batchnorm apply + relu (in place, float4) ----------------
template<int WHICH>
__global__ void k_bnapply(const float* __restrict__ g, const float* __restrict__ bb) {
    float* x = (WHICH == 0) ? g_X1 : g_X0;
    int i4 = blockIdx.x * blockDim.x + threadIdx.x;      // float4 index
    if (i4 >= NIMG*HW*NC/4) return;
    int c0 = (i4*4) & 127;
    const float invN = 1.f / (float)(NIMG*HW);
    float4 v = *reinterpret_cast<float4*>(&x[i4*4]);
    float r[4] = {v.x, v.y, v.z, v.w};
    #pragma unroll
    for (int j = 0; j < 4; j++) {
        int c = c0 + j;
        float m  = g_bn_sum[c] * invN;
        float vv = g_bn_sumsq[c] * invN - m*m;
        float sc = g[c] / sqrtf(vv + 1e-5f);
        r[j] = fmaxf((r[j] - m) * sc + bb[c], 0.f);
    }
    *reinterpret_cast<float4*>(&x[i4*4]) = make_float4(r[0], r[1], r[2], r[3]);
}

// ---------------- max over HW then relu -> obs_feat ----------------
__global__ void k_maxpool() {
    int n = blockIdx.x, c = threadIdx.x;
    const float* p = g_X0 + (size_t)n * HW * NC;
    float m = p[c];
    for (int i = 1; i < HW; i++) m = fmaxf(m, p[i*NC + c]);
    g_obs_feat[n*NC + c] = fmaxf(m, 0.f);
}

// ---------------- gi = obs_feat @ Wih^T + bih, batched once ----------------
__global__ __launch_bounds__(192) void k_gi(const float* __restrict__ wih,
                                            const float* __restrict__ bih) {
    int n0 = blockIdx.x * 8;           // 512 blocks, 8 rows each
    int j = threadIdx.x;               // 192 output cols
    __shared__ float xs[8*128];
    for (int i = j; i < 1024; i += 192) xs[i] = g_obs_feat[n0*128 + i];
    __syncthreads();
    float acc[8];
    float bv = bih[j];
    #pragma unroll
    for (int r = 0; r < 8; r++) acc[r] = bv;
    for (int i = 0; i < 128; i++) {
        float wv = wih[j*128 + i];
        #pragma unroll
        for (int r = 0; r < 8; r++) acc[r] += xs[r*128 + i] * wv;
    }
    #pragma unroll
    for (int r = 0; r < 8; r++) g_gi[(n0 + r)*192 + j] = acc[r];
}

// ---------------- per-step: GRU recurrent part + z projection -------------
__global__ void k_gruz(int t,
                       const float* __restrict__ whh, const float* __restrict__ bhh,
                       const float* __restrict__ prew, const float* __restrict__ preb) {
    int b = blockIdx.x;        // 64
    int tid = threadIdx.x;     // 512
    if (b == 0) g_counts[tid] = 0.f;
    g_sums[b*512 + tid] = 0.f;
    __shared__ float hs[64], gsum[192], hn_[64];
    if (tid < 64)  hs[tid] = g_h[b*64 + tid];
    __syncthreads();
    if (tid < 192) {
        float a = bhh[tid];
        for (int i = 0; i < 64; i++) a += hs[i] * whh[tid*64 + i];
        gsum[tid] = a;         // gh; gi added below
    }
    __syncthreads();
    if (tid < 64) {
        const float* gi = g_gi + (b*64 + t)*192;
        float r  = 1.f / (1.f + expf(-(gi[tid]       + gsum[tid])));
        float zz = 1.f / (1.f + expf(-(gi[64 + tid]  + gsum[64 + tid])));
        float nn = tanhf(gi[128 + tid] + r * gsum[128 + tid]);
        float h  = (1.f - zz) * nn + zz * hs[tid];
        hn_[tid] = h;
        g_h[b*64 + tid] = h;
    }
    __syncthreads();
    float a = preb[tid];
    for (int i = 0; i < 64; i++) a += hn_[i] * prew[i*512 + tid];
    g_z[b*512 + tid] = a;
}

// ---------------- VQ stage 1: per (s, k-chunk) partial argmin -------------
__global__ __launch_bounds__(256) void k_vqpart() {
    int s  = blockIdx.x >> 3;
    int kc = blockIdx.x & 7;
    int tid = threadIdx.x;             // 256
    __shared__ float cbs[64*64];       // chunk [k][e]
    __shared__ float zsh[64*64];       // transposed [e][b]
    __shared__ float pd[4*64];
    __shared__ int   pi[4*64];
    // load cb chunk (coalesced float4)
    const float4* cb4 = reinterpret_cast<const float4*>(g_cb + ((size_t)s*NK + kc*64)*NE);
    float4* cbs4 = reinterpret_cast<float4*>(cbs);
    #pragma unroll
    for (int j = 0; j < 4; j++) cbs4[tid + j*256] = cb4[tid + j*256];
    // load z for this s, transposed into [e][b]
    for (int j = tid; j < 4096; j += 256) {
        int bb = j >> 6, e = j & 63;
        zsh[e*64 + bb] = g_z[bb*512 + s*64 + e];
    }
    __syncthreads();
    int b  = tid & 63;
    int kg = tid >> 6;                 // 0..3, 16 k each
    float zreg[64];
    #pragma unroll
    for (int e = 0; e < 64; e++) zreg[e] = zsh[e*64 + b];
    float best = 3.4e38f; int bk = 0;
    #pragma unroll 4
    for (int j = 0; j < 16; j++) {
        int kl = kg*16 + j;
        const float4* row = reinterpret_cast<const float4*>(cbs + kl*64);
        float d = 0.f;
        #pragma unroll
        for (int e4 = 0; e4 < 16; e4++) {
            float4 c = row[e4];
            float dx = zreg[4*e4]   - c.x; d = fmaf(dx, dx, d);
            dx = zreg[4*e4+1] - c.y; d = fmaf(dx, dx, d);
            dx = zreg[4*e4+2] - c.z; d = fmaf(dx, dx, d);
            dx = zreg[4*e4+3] - c.w; d = fmaf(dx, dx, d);
        }
        if (d < best) { best = d; bk = kl; }
    }
    pd[kg*64 + b] = best; pi[kg*64 + b] = bk;
    __syncthreads();
    if (tid < 64) {
        float bd = pd[tid]; int bi = pi[tid];
        #pragma unroll
        for (int g = 1; g < 4; g++) {
            float d2 = pd[g*64 + tid];
            if (d2 < bd) { bd = d2; bi = pi[g*64 + tid]; }
        }
        g_pd[blockIdx.x*64 + tid] = bd;
        g_pi[blockIdx.x*64 + tid] = kc*64 + bi;
    }
}

// ---------------- VQ stage 2 + stats + FiLM MLP (per b) -------------------
__global__ __launch_bounds__(256) void k_step2(int t,
        const float* __restrict__ m1w, const float* __restrict__ m1b,
        const float* __restrict__ m2w, const float* __restrict__ m2b) {
    int b = blockIdx.x;                // 64
    int tid = threadIdx.x;             // 256
    __shared__ int   kmin[8];
    __shared__ float dmin[8];
    __shared__ float zq[512], h1[128];
    if (tid < 8) {
        int s = tid;
        float bd = 3.4e38f; int bi = 0;
        #pragma unroll
        for (int kc = 0; kc < 8; kc++) {
            float d = g_pd[(s*8 + kc)*64 + b];
            if (d < bd) { bd = d; bi = g_pi[(s*8 + kc)*64 + b]; }
        }
        kmin[s] = bi; dmin[s] = bd;
        atomicAdd(&g_counts[bi], 1.0f);
    }
    __syncthreads();
    if (tid == 0) {
        double e = 0.0;
        #pragma unroll
        for (int s = 0; s < 8; s++) e += (double)dmin[s];
        atomicAdd(&g_el, e * (1.0 / 32768.0));
    }
    // zq gather (old cb) + sums accumulation
    #pragma unroll
    for (int rep = 0; rep < 2; rep++) {
        int j = tid + rep*256;         // 0..511
        int s = j >> 6, e = j & 63;
        int k = kmin[s];
        zq[j] = g_cb[((size_t)s*NK + k)*NE + e];
        atomicAdd(&g_sums[k*64 + e], g_z[b*512 + j]);
    }
    __syncthreads();
    if (tid < 128) {
        float a = m1b[tid];
        for (int i = 0; i < 512; i++) a += zq[i] * m1w[i*128 + tid];
        h1[tid] = fmaxf(a, 0.f);
    }
    __syncthreads();
    float a = m2b[tid];
    for (int i = 0; i < 128; i++) a += h1[i] * m2w[i*256 + tid];
    if (tid < 128) g_gab_g[(t*64 + b)*128 + tid] = 1.f + a;
    else           g_gab_b[(t*64 + b)*128 + (tid - 128)] = a;
}

// ---------------- EMA codebook update, parallel (ping-pong cs) ------------
__global__ __launch_bounds__(256) void k_cbup(int t) {
    int s  = blockIdx.x >> 3;          // 64 blocks
    int kc = blockIdx.x & 7;
    int tid = threadIdx.x;             // 256
    const float* csr = (t & 1) ? g_csB : g_csA;
    float*       csw = (t & 1) ? g_csA : g_csB;
    __shared__ float red[256];
    __shared__ float csn_ch[64];
    float v1 = csr[s*NK + tid]       * 0.99f + 0.01f * g_counts[tid];
    float v2 = csr[s*NK + tid + 256] * 0.99f + 0.01f * g_counts[tid + 256];
    red[tid] = v1 + v2;
    __syncthreads();
    for (int off = 128; off > 0; off >>= 1) {
        if (tid < off) red[tid] += red[tid + off];
        __syncthreads();
    }
    float ntot = red[0];
    if (tid < 64) {
        int k = kc*64 + tid;
        float cs_new = csr[s*NK + k] * 0.99f + 0.01f * g_counts[k];
        csw[s*NK + k] = cs_new;
        csn_ch[tid] = (cs_new + 1e-5f) / (ntot + 512.f * 1e-5f) * ntot;
    }
    __syncthreads();
    // ea / cb update for this (s, k-chunk): 64k x 64e = 1024 float4
    float4* ea4 = reinterpret_cast<float4*>(g_ea + ((size_t)s*NK + kc*64)*NE);
    float4* cb4 = reinterpret_cast<float4*>(g_cb + ((size_t)s*NK + kc*64)*NE);
    const float4* sm4 = reinterpret_cast<const float4*>(g_sums + kc*64*NE);
    #pragma unroll
    for (int rep = 0; rep < 4; rep++) {
        int j = tid + rep*256;         // float4 index, k_local = j>>4
        float inv = 1.f / csn_ch[j >> 4];
        float4 e = ea4[j], sv = sm4[j];
        e.x = e.x*0.99f + 0.01f*sv.x;  e.y = e.y*0.99f + 0.01f*sv.y;
        e.z = e.z*0.99f + 0.01f*sv.z;  e.w = e.w*0.99f + 0.01f*sv.w;
        ea4[j] = e;
        cb4[j] = make_float4(e.x*inv, e.y*inv, e.z*inv, e.w*inv);
    }
}

// ---------------- batched decoder over all (t,p,b), 16 rows/block ---------
__global__ __launch_bounds__(128) void k_dec(const int* __restrict__ acts,
        const float* __restrict__ w1, const float* __restrict__ b1,
        const float* __restrict__ w2, const float* __restrict__ b2,
        const float* __restrict__ w3, const float* __restrict__ b3) {
    int row0 = blockIdx.x * 16;
    int tp = row0 >> 6;                // (t,p) pair index, rows share tp (64%16==0)
    int b0 = row0 & 63;
    // invert triangular index: base(t) = t*(127-t)/2
    float sq = sqrtf((float)(127*127 - 8*tp));
    int t = (int)((127.0f - sq) * 0.5f);
    while ((t+1)*(127-(t+1))/2 <= tp && t < 62) t++;
    while (t*(127-t)/2 > tp) t--;
    int p = t + (tp - t*(127-t)/2);
    int c = threadIdx.x;               // 128
    __shared__ float f[16][128];
    __shared__ float h1[16][128];
    __shared__ float h2[16][128];
    __shared__ float lg[16][6];
    __shared__ float ce[16];
    #pragma unroll
    for (int j = 0; j < 16; j++) {
        int b = b0 + j;
        float of = g_obs_feat[(b*64 + p)*NC + c];
        float fl = of * g_gab_g[(t*64 + b)*128 + c] + g_gab_b[(t*64 + b)*128 + c];
        f[j][c] = fmaxf(fl, 0.f);
    }
    __syncthreads();
    float acc[16];
    float bv = b1[c];
    #pragma unroll
    for (int j = 0; j < 16; j++) acc[j] = bv;
    for (int i = 0; i < 128; i++) {
        float wv = w1[i*128 + c];
        #pragma unroll
        for (int j = 0; j < 16; j++) acc[j] += f[j][i] * wv;
    }
    #pragma unroll
    for (int j = 0; j < 16; j++) h1[j][c] = fmaxf(acc[j], 0.f);
    __syncthreads();
    bv = b2[c];
    #pragma unroll
    for (int j = 0; j < 16; j++) acc[j] = bv;
    for (int i = 0; i < 128; i++) {
        float wv = w2[i*128 + c];
        #pragma unroll
        for (int j = 0; j < 16; j++) acc[j] += h1[j][i] * wv;
    }
    #pragma unroll
    for (int j = 0; j < 16; j++) h2[j][c] = fmaxf(acc[j], 0.f);
    __syncthreads();
    if (c < 96) {
        int j = c / 6, o = c % 6;
        float l = b3[o];
        for (int i = 0; i < 128; i++) l += h2[j][i] * w3[i*6 + o];
        lg[j][o] = l;
    }
    __syncthreads();
    if (c < 16) {
        int b = b0 + c;
        float m = lg[c][0];
        #pragma unroll
        for (int i = 1; i < 6; i++) m = fmaxf(m, lg[c][i]);
        float se = 0.f;
        #pragma unroll
        for (int i = 0; i < 6; i++) se += expf(lg[c][i] - m);
        float lse = m + logf(se);
        int a = acts[b*63 + p];
        ce[c] = lse - lg[c][a];
    }
    __syncthreads();
    if (c == 0) {
        double ssum = 0.0;
        #pragma unroll
        for (int j = 0; j < 16; j++) ssum += (double)ce[j];
        atomicAdd(&g_decl, ssum);
    }
}

// ---------------- finalize ----------------
__global__ void k_final(float* __restrict__ out) {
    if (threadIdx.x == 0) {
        out[0] = (float)(g_decl / 64.0);
        out[1] = (float)(g_el / 64.0);
    }
}

// ---------------- launch ----------------
extern "C" void kernel_launch(void* const* d_in, const int* in_sizes, int n_in,
                              void* d_out, int out_size) {
    const int*   obs  = (const int*)d_in[0];
    const int*   acts = (const int*)d_in[1];
    const float* emb  = (const float*)d_in[2];
    const float* c1w  = (const float*)d_in[3];
    const float* c1b  = (const float*)d_in[4];
    const float* bn1g = (const float*)d_in[5];
    const float* bn1b = (const float*)d_in[6];
    const float* c2w  = (const float*)d_in[7];
    const float* c2b  = (const float*)d_in[8];
    const float* bn2g = (const float*)d_in[9];
    const float* bn2b = (const float*)d_in[10];
    const float* wih  = (const float*)d_in[11];
    const float* whh  = (const float*)d_in[12];
    const float* bih  = (const float*)d_in[13];
    const float* bhh  = (const float*)d_in[14];
    const float* prew = (const float*)d_in[15];
    const float* preb = (const float*)d_in[16];
    const float* cbk  = (const float*)d_in[17];
    const float* m1w  = (const float*)d_in[18];
    const float* m1b  = (const float*)d_in[19];
    const float* m2w  = (const float*)d_in[20];
    const float* m2b  = (const float*)d_in[21];
    const float* d1w  = (const float*)d_in[22];
    const float* d1b  = (const float*)d_in[23];
    const float* d2w  = (const float*)d_in[24];
    const float* d2b  = (const float*)d_in[25];
    const float* d3w  = (const float*)d_in[26];
    const float* d3b  = (const float*)d_in[27];
    float* out = (float*)d_out;

    k_init<<<512, 512>>>(cbk);
    k_embed<<<NIMG, 128>>>(obs, emb);
    k_conv<0><<<NIMG, 128>>>(c1w, c1b);
    k_bnstat<0><<<NIMG/16, 128>>>();
    k_bnapply<0><<<(NIMG*HW*NC/4 + 255) / 256, 256>>>(bn1g, bn1b);
    k_conv<1><<<NIMG, 128>>>(c2w, c2b);
    k_bnstat<1><<<NIMG/16, 128>>>();
    k_bnapply<1><<<(NIMG*HW*NC/4 + 255) / 256, 256>>>(bn2g, bn2b);
    k_maxpool<<<NIMG, 128>>>();
    k_gi<<<NIMG/8, 192>>>(wih, bih);

    for (int t = 0; t < NT; t++) {
        k_gruz<<<NB, 512>>>(t, whh, bhh, prew, preb);
        k_vqpart<<<64, 256>>>();
        k_step2<<<NB, 256>>>(t, m1w, m1b, m2w, m2b);
        k_cbup<<<64, 256>>>(t);
    }
    k_dec<<<129024/16, 128>>>(acts, d1w, d1b, d2w, d2b, d3w, d3b);
    k_final<<<1, 32>>>(out);
}

// round 6
// speedup vs baseline: 3.0895x; 1.0238x over previous
#include <cuda_runtime.h>
#include <math.h>

// Problem constants
#define NB    64
#define NIMG  4096    // NB*64
#define HW    49
#define NC    128
#define NS    8
#define NK    512
#define NE    64
#define NT    63

#define CONV_SMEM (128*108*4 + 3*49*4 + 16)   // patch + sidx

typedef unsigned long long ull;

__device__ __forceinline__ ull packf2(float lo, float hi) {
    ull d;
    asm("mov.b64 %0, {%1, %2};" : "=l"(d)
        : "r"(__float_as_uint(lo)), "r"(__float_as_uint(hi)));
    return d;
}
__device__ __forceinline__ void unpackf2(ull d, float& lo, float& hi) {
    unsigned int a, b;
    asm("mov.b64 {%0, %1}, %2;" : "=r"(a), "=r"(b) : "l"(d));
    lo = __uint_as_float(a); hi = __uint_as_float(b);
}
#define FFMA2(d, a, b) asm("fma.rn.f32x2 %0, %1, %2, %0;" : "+l"(d) : "l"(a), "l"(b))

// ---------------- device scratch ----------------
__device__ float g_X1[NIMG*HW*NC];     // conv1 output (~98MB)
__device__ float g_cmax[NIMG*NC];
__device__ float g_cmin[NIMG*NC];
__device__ float g_obs_feat[NIMG*NC];
__device__ float g_gi[NIMG*192];
__device__ float g_bn1_sum[NC];
__device__ float g_bn1_sq[NC];
__device__ float g_bn2_sum[NC];
__device__ float g_bn2_sq[NC];
__device__ float g_h[NB*64];
__device__ float g_z[NB*512];
__device__ float g_cb[NS*NK*NE];
__device__ float g_csA[NS*NK];
__device__ float g_csB[NS*NK];
__device__ float g_ea[NS*NK*NE];
__device__ float g_cntA[NK];
__device__ float g_cntB[NK];
__device__ float g_sumA[NK*NE];
__device__ float g_sumB[NK*NE];
__device__ float g_pd[64*64];
__device__ int   g_pi[64*64];
__device__ float g_gab_g[NT*NB*NC];
__device__ float g_gab_b[NT*NB*NC];
__device__ double g_decl;
__device__ double g_el;

// ---------------- init (split so conv1 is ncu launch #6) ----------
__global__ void k_init_a(const float* __restrict__ codebook) {
    int i = blockIdx.x * blockDim.x + threadIdx.x;
    if (i < NS*NK*NE) { g_cb[i] = codebook[i]; g_ea[i] = codebook[i]; }
}
__global__ void k_init_b() {
    int i = blockIdx.x * blockDim.x + threadIdx.x;
    if (i < NS*NK) { g_csA[i] = 0.f; g_csB[i] = 0.f; }
    if (i < NB*64) g_h[i] = 0.f;
    if (i < NC) { g_bn1_sum[i]=0.f; g_bn1_sq[i]=0.f; g_bn2_sum[i]=0.f; g_bn2_sq[i]=0.f; }
    if (i == 0) { g_decl = 0.0; g_el = 0.0; }
}
__global__ void k_init_c() {
    int i = blockIdx.x * blockDim.x + threadIdx.x;
    if (i < NK) { g_cntA[i] = 0.f; g_cntB[i] = 0.f; }
}
__global__ void k_init_d() {
    int i = blockIdx.x * blockDim.x + threadIdx.x;
    if (i < NK*NE) g_sumA[i] = 0.f;
}
__global__ void k_init_e() {
    int i = blockIdx.x * blockDim.x + threadIdx.x;
    if (i < NK*NE) g_sumB[i] = 0.f;
}

// ---------------- fused conv: 3x3 SAME, 128->128, packed f32x2 FMAs --------
// MODE 0: input = embedding gather; output -> g_X1 + bn1 stats atomics.
// MODE 1: input = bn1-applied relu of g_X1; output -> per-image min/max + bn2 stats.
// Dynamic smem: P[ci][9 rows][12 padded cols] then sidx[3*49].
template<int MODE>
__global__ __launch_bounds__(128) void k_conv(
        const int* __restrict__ obs, const float* __restrict__ emb,
        const float* __restrict__ w, const float* __restrict__ bias,
        const float* __restrict__ bng, const float* __restrict__ bnb) {
    extern __shared__ float P[];                 // 128*108 floats
    int* sidx = (int*)(P + 128*108);             // 3*49 ints
    int n  = blockIdx.x;
    int co = threadIdx.x;

    // zero own row (includes pad)
    #pragma unroll
    for (int q = 0; q < 108; q++) P[co*108 + q] = 0.f;

    if (MODE == 0) {
        int b = n >> 6, t = n & 63;
        for (int j = co; j < 3*HW; j += 128) {
            int pl = j / HW, pos = j % HW;
            sidx[j] = obs[(((b*65 + t)*3 + pl)*HW) + pos] + pl * 147;
        }
        __syncthreads();
        #pragma unroll 7
        for (int pos = 0; pos < HW; pos++) {
            float v = emb[sidx[pos]*NC + co]
                    + emb[sidx[HW + pos]*NC + co]
                    + emb[sidx[2*HW + pos]*NC + co];
            int h = pos / 7, wv = pos % 7;
            P[co*108 + (h+1)*12 + (wv+1)] = v;
        }
    } else {
        const float invN = 1.f / 200704.f;
        float m  = g_bn1_sum[co] * invN;
        float va = g_bn1_sq[co] * invN - m*m;
        float sc = bng[co] * rsqrtf(va + 1e-5f);
        float sh = bnb[co] - m * sc;
        const float* inp = g_X1 + (size_t)n * HW * NC;
        #pragma unroll 7
        for (int pos = 0; pos < HW; pos++) {
            float v = fmaxf(fmaf(inp[pos*NC + co], sc, sh), 0.f);
            int h = pos / 7, wv = pos % 7;
            P[co*108 + (h+1)*12 + (wv+1)] = v;
        }
        __syncthreads();
    }
    if (MODE == 0) __syncthreads();

    float bv = bias[co];
    ull  acc2[7][3];
    float accs[7];
    ull bvp = packf2(bv, bv);
    #pragma unroll
    for (int oh = 0; oh < 7; oh++) {
        accs[oh] = bv;
        #pragma unroll
        for (int j = 0; j < 3; j++) acc2[oh][j] = bvp;
    }

    for (int ci = 0; ci < NC; ci++) {
        float wt[9]; ull wp[9];
        #pragma unroll
        for (int tap = 0; tap < 9; tap++) {
            float wv = w[(tap*NC + ci)*NC + co];
            wt[tap] = wv; wp[tap] = packf2(wv, wv);
        }
        const float* rowp = &P[ci*108];
        #pragma unroll
        for (int r = 0; r < 9; r++) {
            float4 ra = *reinterpret_cast<const float4*>(rowp + r*12);
            float4 rb = *reinterpret_cast<const float4*>(rowp + r*12 + 4);
            float e8 = rowp[r*12 + 8];
            ull E0 = packf2(ra.x, ra.y), E1 = packf2(ra.z, ra.w);
            ull E2 = packf2(rb.x, rb.y), E3 = packf2(rb.z, rb.w);
            ull O0 = packf2(ra.y, ra.z), O1 = packf2(ra.w, rb.x);
            ull O2 = packf2(rb.y, rb.z);
            #pragma unroll
            for (int kh = 0; kh < 3; kh++) {
                int oh = r - kh;
                if (oh < 0 || oh > 6) continue;
                // kw = 0
                FFMA2(acc2[oh][0], E0, wp[kh*3+0]);
                FFMA2(acc2[oh][1], E1, wp[kh*3+0]);
                FFMA2(acc2[oh][2], E2, wp[kh*3+0]);
                accs[oh] = fmaf(rb.z, wt[kh*3+0], accs[oh]);
                // kw = 1
                FFMA2(acc2[oh][0], O0, wp[kh*3+1]);
                FFMA2(acc2[oh][1], O1, wp[kh*3+1]);
                FFMA2(acc2[oh][2], O2, wp[kh*3+1]);
                accs[oh] = fmaf(rb.w, wt[kh*3+1], accs[oh]);
                // kw = 2
                FFMA2(acc2[oh][0], E1, wp[kh*3+2]);
                FFMA2(acc2[oh][1], E2, wp[kh*3+2]);
                FFMA2(acc2[oh][2], E3, wp[kh*3+2]);
                accs[oh] = fmaf(e8, wt[kh*3+2], accs[oh]);
            }
        }
    }

    // epilogue
    float s = 0.f, s2 = 0.f;
    float mx = -3.4e38f, mn = 3.4e38f;
    float* op = (MODE == 0) ? (g_X1 + (size_t)n * HW * NC) : (float*)0;
    #pragma unroll
    for (int oh = 0; oh < 7; oh++) {
        float v[7];
        unpackf2(acc2[oh][0], v[0], v[1]);
        unpackf2(acc2[oh][1], v[2], v[3]);
        unpackf2(acc2[oh][2], v[4], v[5]);
        v[6] = accs[oh];
        #pragma unroll
        for (int ow = 0; ow < 7; ow++) {
            float x = v[ow];
            s += x; s2 = fmaf(x, x, s2);
            if (MODE == 0) op[(oh*7 + ow)*NC + co] = x;
            else { mx = fmaxf(mx, x); mn = fminf(mn, x); }
        }
    }
    if (MODE == 0) {
        atomicAdd(&g_bn1_sum[co], s);
        atomicAdd(&g_bn1_sq[co], s2);
    } else {
        g_cmax[n*NC + co] = mx;
        g_cmin[n*NC + co] = mn;
        atomicAdd(&g_bn2_sum[co], s);
        atomicAdd(&g_bn2_sq[co], s2);
    }
}

// ---------------- bn2 + maxpool + relu -> obs_feat ----------------
__global__ void k_bn2max(const float* __restrict__ bng, const float* __restrict__ bnb) {
    int i = blockIdx.x * blockDim.x + threadIdx.x;
    if (i >= NIMG*NC) return;
    int c = i & 127;
    const float invN = 1.f / 200704.f;
    float m  = g_bn2_sum[c] * invN;
    float va = g_bn2_sq[c] * invN - m*m;
    float sc = bng[c] * rsqrtf(va + 1e-5f);
    float sh = bnb[c] - m * sc;
    float raw = (sc >= 0.f) ? g_cmax[i] : g_cmin[i];
    g_obs_feat[i] = fmaxf(fmaf(raw, sc, sh), 0.f);
}

// ---------------- gi = obs_feat @ Wih^T + bih, batched once ----------------
__global__ __launch_bounds__(192) void k_gi(const float* __restrict__ wih,
                                            const float* __restrict__ bih) {
    int n0 = blockIdx.x * 8;
    int j = threadIdx.x;
    __shared__ float xs[8*128];
    for (int i = j; i < 1024; i += 192) xs[i] = g_obs_feat[n0*128 + i];
    __syncthreads();
    float acc[8];
    float bv = bih[j];
    #pragma unroll
    for (int r = 0; r < 8; r++) acc[r] = bv;
    for (int i = 0; i < 128; i++) {
        float wv = wih[j*128 + i];
        #pragma unroll
        for (int r = 0; r < 8; r++) acc[r] = fmaf(xs[r*128 + i], wv, acc[r]);
    }
    #pragma unroll
    for (int r = 0; r < 8; r++) g_gi[(n0 + r)*192 + j] = acc[r];
}

// ---------------- GRU step 0 (h=0) + z(0) ----------------
__global__ __launch_bounds__(256) void k_gruz0(const float* __restrict__ bhh,
        const float* __restrict__ prew, const float* __restrict__ preb) {
    int b = blockIdx.x, tid = threadIdx.x;
    __shared__ float gh[192], hn[64];
    if (tid < 192) gh[tid] = bhh[tid];
    __syncthreads();
    if (tid < 64) {
        const float* gi = g_gi + (size_t)(b*64)*192;
        float zz = 1.f / (1.f + expf(-(gi[64 + tid] + gh[64 + tid])));
        float r  = 1.f / (1.f + expf(-(gi[tid] + gh[tid])));
        float nn = tanhf(gi[128 + tid] + r * gh[128 + tid]);
        float h = (1.f - zz) * nn;
        hn[tid] = h; g_h[b*64 + tid] = h;
    }
    __syncthreads();
    #pragma unroll
    for (int rep = 0; rep < 2; rep++) {
        int j = tid + rep*256;
        float a = preb[j];
        for (int i = 0; i < 64; i++) a = fmaf(hn[i], prew[i*512 + j], a);
        g_z[b*512 + j] = a;
    }
}

// ---------------- fuse1: cb EMA update (prev step stats) + VQ partial -----
__global__ __launch_bounds__(256) void k_fuse1(int t) {
    int s = blockIdx.x >> 3, kc = blockIdx.x & 7, tid = threadIdx.x;
    __shared__ float cbs[64*64];
    __shared__ float zsh[64*65];
    __shared__ float red[256];
    __shared__ float invc[64];
    __shared__ float pdl[4*64];
    __shared__ int   pil[4*64];

    const float* csr  = (t & 1) ? g_csB : g_csA;   // state(t-2)
    float*       csw  = (t & 1) ? g_csA : g_csB;   // state(t-1)
    const float* cntp = (t & 1) ? g_cntA : g_cntB; // stats of step t-1
    const float* sump = (t & 1) ? g_sumA : g_sumB;
    float*       cntc = (t & 1) ? g_cntB : g_cntA; // will hold stats of step t
    float*       sumc = (t & 1) ? g_sumB : g_sumA;

    // zero current-step stat buffers (64 blocks partition them)
    if (tid < 8) cntc[blockIdx.x*8 + tid] = 0.f;
    if (tid < 128) reinterpret_cast<float4*>(sumc + blockIdx.x*512)[tid] = make_float4(0,0,0,0);

    // load z (transposed, padded)
    #pragma unroll
    for (int rep = 0; rep < 16; rep++) {
        int j = tid + rep*256;
        int bb = j >> 6, e = j & 63;
        zsh[e*65 + bb] = g_z[bb*512 + s*64 + e];
    }

    if (t > 0) {
        float c1 = fmaf(0.01f, cntp[tid],       csr[s*NK + tid]       * 0.99f);
        float c2 = fmaf(0.01f, cntp[tid + 256], csr[s*NK + tid + 256] * 0.99f);
        red[tid] = c1 + c2;
        __syncthreads();
        for (int off = 128; off > 0; off >>= 1) {
            if (tid < off) red[tid] += red[tid + off];
            __syncthreads();
        }
        float ntot = red[0];
        if (tid < 64) {
            int k = kc*64 + tid;
            float cs_new = fmaf(0.01f, cntp[k], csr[s*NK + k] * 0.99f);
            csw[s*NK + k] = cs_new;
            float csn = (cs_new + 1e-5f) / (ntot + 512.f * 1e-5f) * ntot;
            invc[tid] = 1.f / csn;
        }
        __syncthreads();
        float4* ea4  = reinterpret_cast<float4*>(g_ea + ((size_t)s*NK + kc*64)*NE);
        float4* cbg4 = reinterpret_cast<float4*>(g_cb + ((size_t)s*NK + kc*64)*NE);
        const float4* sm4 = reinterpret_cast<const float4*>(sump + kc*64*NE);
        float4* cbs4 = reinterpret_cast<float4*>(cbs);
        #pragma unroll
        for (int rep = 0; rep < 4; rep++) {
            int j = tid + rep*256;
            float inv = invc[j >> 4];
            float4 e = ea4[j], sv = sm4[j];
            e.x = fmaf(0.01f, sv.x, e.x*0.99f);
            e.y = fmaf(0.01f, sv.y, e.y*0.99f);
            e.z = fmaf(0.01f, sv.z, e.z*0.99f);
            e.w = fmaf(0.01f, sv.w, e.w*0.99f);
            ea4[j] = e;
            float4 cv = make_float4(e.x*inv, e.y*inv, e.z*inv, e.w*inv);
            cbg4[j] = cv;
            cbs4[j] = cv;
        }
    } else {
        const float4* cbg4 = reinterpret_cast<const float4*>(g_cb + ((size_t)s*NK + kc*64)*NE);
        float4* cbs4 = reinterpret_cast<float4*>(cbs);
        #pragma unroll
        for (int rep = 0; rep < 4; rep++) cbs4[tid + rep*256] = cbg4[tid + rep*256];
    }
    __syncthreads();

    // partial argmin over this 64-code chunk
    int b  = tid & 63;
    int kg = tid >> 6;
    float zreg[64];
    #pragma unroll
    for (int e = 0; e < 64; e++) zreg[e] = zsh[e*65 + b];
    float best = 3.4e38f; int bk = 0;
    #pragma unroll 4
    for (int j = 0; j < 16; j++) {
        int kl = kg*16 + j;
        const float4* row = reinterpret_cast<const float4*>(cbs + kl*64);
        float d = 0.f;
        #pragma unroll
        for (int e4 = 0; e4 < 16; e4++) {
            float4 c = row[e4];
            float dx = zreg[4*e4]   - c.x; d = fmaf(dx, dx, d);
            dx = zreg[4*e4+1] - c.y; d = fmaf(dx, dx, d);
            dx = zreg[4*e4+2] - c.z; d = fmaf(dx, dx, d);
            dx = zreg[4*e4+3] - c.w; d = fmaf(dx, dx, d);
        }
        if (d < best) { best = d; bk = kl; }
    }
    pdl[kg*64 + b] = best; pil[kg*64 + b] = bk;
    __syncthreads();
    if (tid < 64) {
        float bd = pdl[tid]; int bi = pil[tid];
        #pragma unroll
        for (int g = 1; g < 4; g++) {
            float d2 = pdl[g*64 + tid];
            if (d2 < bd) { bd = d2; bi = pil[g*64 + tid]; }
        }
        g_pd[blockIdx.x*64 + tid] = bd;
        g_pi[blockIdx.x*64 + tid] = kc*64 + bi;
    }
}

// ---------------- fuse2: argmin finalize + stats + MLP + GRU(t+1) ---------
__global__ __launch_bounds__(256) void k_fuse2(int t,
        const float* __restrict__ m1w, const float* __restrict__ m1b,
        const float* __restrict__ m2w, const float* __restrict__ m2b,
        const float* __restrict__ whh, const float* __restrict__ bhh,
        const float* __restrict__ prew, const float* __restrict__ preb) {
    int b = blockIdx.x, tid = threadIdx.x;
    float* cntc = (t & 1) ? g_cntB : g_cntA;
    float* sumc = (t & 1) ? g_sumB : g_sumA;
    __shared__ int   kmin[8];
    __shared__ float dmin[8];
    __shared__ float zq[512], h1[128], hs[64], gh[192], hn[64];

    if (tid < 64) hs[tid] = g_h[b*64 + tid];
    if (tid < 8) {
        int s = tid;
        float bd = 3.4e38f; int bi = 0;
        #pragma unroll
        for (int kc = 0; kc < 8; kc++) {
            float d = g_pd[(s*8 + kc)*64 + b];
            if (d < bd) { bd = d; bi = g_pi[(s*8 + kc)*64 + b]; }
        }
        kmin[s] = bi; dmin[s] = bd;
        atomicAdd(&cntc[bi], 1.0f);
    }
    __syncthreads();
    if (tid == 0) {
        double e = 0.0;
        #pragma unroll
        for (int s = 0; s < 8; s++) e += (double)dmin[s];
        atomicAdd(&g_el, e * (1.0 / 32768.0));
    }
    #pragma unroll
    for (int rep = 0; rep < 2; rep++) {
        int j = tid + rep*256;
        int s = j >> 6, e = j & 63;
        int k = kmin[s];
        zq[j] = g_cb[((size_t)s*NK + k)*NE + e];
        atomicAdd(&sumc[k*64 + e], g_z[b*512 + j]);
    }
    __syncthreads();
    if (tid < 128) {
        float a = m1b[tid];
        for (int i = 0; i < 512; i += 4) {
            float4 zv = *reinterpret_cast<const float4*>(&zq[i]);
            a = fmaf(zv.x, m1w[i*128 + tid], a);
            a = fmaf(zv.y, m1w[(i+1)*128 + tid], a);
            a = fmaf(zv.z, m1w[(i+2)*128 + tid], a);
            a = fmaf(zv.w, m1w[(i+3)*128 + tid], a);
        }
        h1[tid] = fmaxf(a, 0.f);
    }
    __syncthreads();
    {
        float a = m2b[tid];
        for (int i = 0; i < 128; i++) a = fmaf(h1[i], m2w[i*256 + tid], a);
        if (tid < 128) g_gab_g[((size_t)t*64 + b)*128 + tid] = 1.f + a;
        else           g_gab_b[((size_t)t*64 + b)*128 + (tid - 128)] = a;
    }
    if (t < 62) {
        __syncthreads();
        if (tid < 192) {
            float a = bhh[tid];
            for (int i = 0; i < 64; i++) a = fmaf(hs[i], whh[tid*64 + i], a);
            gh[tid] = a;
        }
        __syncthreads();
        if (tid < 64) {
            const float* gi = g_gi + ((size_t)(b*64 + t + 1))*192;
            float r  = 1.f / (1.f + expf(-(gi[tid] + gh[tid])));
            float zz = 1.f / (1.f + expf(-(gi[64 + tid] + gh[64 + tid])));
            float nn = tanhf(gi[128 + tid] + r * gh[128 + tid]);
            float h = (1.f - zz) * nn + zz * hs[tid];
            hn[tid] = h; g_h[b*64 + tid] = h;
        }
        __syncthreads();
        #pragma unroll
        for (int rep = 0; rep < 2; rep++) {
            int j = tid + rep*256;
            float a = preb[j];
            for (int i = 0; i < 64; i++) a = fmaf(hn[i], prew[i*512 + j], a);
            g_z[b*512 + j] = a;
        }
    }
}

// ---------------- batched decoder, 16 rows/block, float4 inner ------------
__global__ __launch_bounds__(128) void k_dec(const int* __restrict__ acts,
        const float* __restrict__ w1, const float* __restrict__ b1,
        const float* __restrict__ w2, const float* __restrict__ b2,
        const float* __restrict__ w3, const float* __restrict__ b3) {
    int row0 = blockIdx.x * 16;
    int tp = row0 >> 6;
    int b0 = row0 & 63;
    float sq = sqrtf((float)(127*127 - 8*tp));
    int t = (int)((127.0f - sq) * 0.5f);
    while ((t+1)*(127-(t+1))/2 <= tp && t < 62) t++;
    while (t*(127-t)/2 > tp) t--;
    int p = t + (tp - t*(127-t)/2);
    int c = threadIdx.x;
    __shared__ float f[16][128];
    __shared__ float h1[16][128];
    __shared__ float h2[16][128];
    __shared__ float lg[16][6];
    __shared__ float ce[16];
    #pragma unroll
    for (int j = 0; j < 16; j++) {
        int b = b0 + j;
        float of = g_obs_feat[(b*64 + p)*NC + c];
        float fl = fmaf(of, g_gab_g[((size_t)t*64 + b)*128 + c],
                            g_gab_b[((size_t)t*64 + b)*128 + c]);
        f[j][c] = fmaxf(fl, 0.f);
    }
    __syncthreads();
    float acc[16];
    float bv = b1[c];
    #pragma unroll
    for (int j = 0; j < 16; j++) acc[j] = bv;
    for (int i = 0; i < 128; i += 4) {
        float wa = w1[i*128 + c], wb = w1[(i+1)*128 + c];
        float wc = w1[(i+2)*128 + c], wd = w1[(i+3)*128 + c];
        #pragma unroll
        for (int j = 0; j < 16; j++) {
            float4 fv = *reinterpret_cast<const float4*>(&f[j][i]);
            acc[j] = fmaf(fv.x, wa, fmaf(fv.y, wb, fmaf(fv.z, wc, fmaf(fv.w, wd, acc[j]))));
        }
    }
    #pragma unroll
    for (int j = 0; j < 16; j++) h1[j][c] = fmaxf(acc[j], 0.f);
    __syncthreads();
    bv = b2[c];
    #pragma unroll
    for (int j = 0; j < 16; j++) acc[j] = bv;
    for (int i = 0; i < 128; i += 4) {
        float wa = w2[i*128 + c], wb = w2[(i+1)*128 + c];
        float wc = w2[(i+2)*128 + c], wd = w2[(i+3)*128 + c];
        #pragma unroll
        for (int j = 0; j < 16; j++) {
            float4 fv = *reinterpret_cast<const float4*>(&h1[j][i]);
            acc[j] = fmaf(fv.x, wa, fmaf(fv.y, wb, fmaf(fv.z, wc, fmaf(fv.w, wd, acc[j]))));
        }
    }
    #pragma unroll
    for (int j = 0; j < 16; j++) h2[j][c] = fmaxf(acc[j], 0.f);
    __syncthreads();
    if (c < 96) {
        int j = c / 6, o = c % 6;
        float l = b3[o];
        for (int i = 0; i < 128; i++) l = fmaf(h2[j][i], w3[i*6 + o], l);
        lg[j][o] = l;
    }
    __syncthreads();
    if (c < 16) {
        int b = b0 + c;
        float m = lg[c][0];
        #pragma unroll
        for (int i = 1; i < 6; i++) m = fmaxf(m, lg[c][i]);
        float se = 0.f;
        #pragma unroll
        for (int i = 0; i < 6; i++) se += expf(lg[c][i] - m);
        float lse = m + logf(se);
        int a = acts[b*63 + p];
        ce[c] = lse - lg[c][a];
    }
    __syncthreads();
    if (c == 0) {
        double ssum = 0.0;
        #pragma unroll
        for (int j = 0; j < 16; j++) ssum += (double)ce[j];
        atomicAdd(&g_decl, ssum);
    }
}

// ---------------- finalize ----------------
__global__ void k_final(float* __restrict__ out) {
    if (threadIdx.x == 0) {
        out[0] = (float)(g_decl / 64.0);
        out[1] = (float)(g_el / 64.0);
    }
}

// ---------------- launch ----------------
extern "C" void kernel_launch(void* const* d_in, const int* in_sizes, int n_in,
                              void* d_out, int out_size) {
    const int*   obs  = (const int*)d_in[0];
    const int*   acts = (const int*)d_in[1];
    const float* emb  = (const float*)d_in[2];
    const float* c1w  = (const float*)d_in[3];
    const float* c1b  = (const float*)d_in[4];
    const float* bn1g = (const float*)d_in[5];
    const float* bn1b = (const float*)d_in[6];
    const float* c2w  = (const float*)d_in[7];
    const float* c2b  = (const float*)d_in[8];
    const float* bn2g = (const float*)d_in[9];
    const float* bn2b = (const float*)d_in[10];
    const float* wih  = (const float*)d_in[11];
    const float* whh  = (const float*)d_in[12];
    const float* bih  = (const float*)d_in[13];
    const float* bhh  = (const float*)d_in[14];
    const float* prew = (const float*)d_in[15];
    const float* preb = (const float*)d_in[16];
    const float* cbk  = (const float*)d_in[17];
    const float* m1w  = (const float*)d_in[18];
    const float* m1b  = (const float*)d_in[19];
    const float* m2w  = (const float*)d_in[20];
    const float* m2b  = (const float*)d_in[21];
    const float* d1w  = (const float*)d_in[22];
    const float* d1b  = (const float*)d_in[23];
    const float* d2w  = (const float*)d_in[24];
    const float* d2b  = (const float*)d_in[25];
    const float* d3w  = (const float*)d_in[26];
    const float* d3b  = (const float*)d_in[27];
    float* out = (float*)d_out;

    // allow >48KB dynamic smem for the conv kernels (host-side attr, capture-safe)
    cudaFuncSetAttribute(k_conv<0>, cudaFuncAttributeMaxDynamicSharedMemorySize, CONV_SMEM);
    cudaFuncSetAttribute(k_conv<1>, cudaFuncAttributeMaxDynamicSharedMemorySize, CONV_SMEM);

    k_init_a<<<1024, 256>>>(cbk);
    k_init_b<<<16, 256>>>();
    k_init_c<<<2, 256>>>();
    k_init_d<<<128, 256>>>();
    k_init_e<<<128, 256>>>();
    k_conv<0><<<NIMG, 128, CONV_SMEM>>>(obs, emb, c1w, c1b, (const float*)0, (const float*)0);
    k_conv<1><<<NIMG, 128, CONV_SMEM>>>(obs, emb, c2w, c2b, bn1g, bn1b);
    k_bn2max<<<(NIMG*NC + 255)/256, 256>>>(bn2g, bn2b);
    k_gi<<<NIMG/8, 192>>>(wih, bih);
    k_gruz0<<<NB, 256>>>(bhh, prew, preb);
    for (int t = 0; t < NT; t++) {
        k_fuse1<<<64, 256>>>(t);
        k_fuse2<<<NB, 256>>>(t, m1w, m1b, m2w, m2b, whh, bhh, prew, preb);
    }
    k_dec<<<129024/16, 128>>>(acts, d1w, d1b, d2w, d2b, d3w, d3b);
    k_final<<<1, 32>>>(out);
}

// round 7
// speedup vs baseline: 3.4280x; 1.1096x over previous
#include <cuda_runtime.h>
#include <math.h>

// Problem constants
#define NB    64
#define NIMG  4096    // NB*64
#define HW    49
#define NC    128
#define NS    8
#define NK    512
#define NE    64
#define NT    63

#define CONV_SMEM (128*108*4 + 3*49*4 + 16)   // patch + sidx

typedef unsigned long long ull;

__device__ __forceinline__ ull packf2(float lo, float hi) {
    ull d;
    asm("mov.b64 %0, {%1, %2};" : "=l"(d)
        : "r"(__float_as_uint(lo)), "r"(__float_as_uint(hi)));
    return d;
}
__device__ __forceinline__ void unpackf2(ull d, float& lo, float& hi) {
    unsigned int a, b;
    asm("mov.b64 {%0, %1}, %2;" : "=r"(a), "=r"(b) : "l"(d));
    lo = __uint_as_float(a); hi = __uint_as_float(b);
}
#define FFMA2(d, a, b) asm("fma.rn.f32x2 %0, %1, %2, %0;" : "+l"(d) : "l"(a), "l"(b))

// ---------------- device scratch ----------------
__device__ float g_X1[NIMG*HW*NC];     // conv1 output (~98MB)
__device__ float g_cmax[NIMG*NC];
__device__ float g_cmin[NIMG*NC];
__device__ float g_obs_feat[NIMG*NC];
__device__ float g_gi[NIMG*192];
__device__ float g_bn1_sum[NC];
__device__ float g_bn1_sq[NC];
__device__ float g_bn2_sum[NC];
__device__ float g_bn2_sq[NC];
__device__ float g_h[NB*64];
__device__ float g_z[NB*512];
__device__ float g_cb[NS*NK*NE];
__device__ float g_csA[NS*NK];
__device__ float g_csB[NS*NK];
__device__ float g_ea[NS*NK*NE];
__device__ float g_cntA[NK];
__device__ float g_cntB[NK];
__device__ float g_sumA[NK*NE];
__device__ float g_sumB[NK*NE];
__device__ float g_pd[64*64];
__device__ int   g_pi[64*64];
__device__ float g_gab_g[NT*NB*NC];
__device__ float g_gab_b[NT*NB*NC];
__device__ double g_decl;
__device__ double g_el;
__device__ unsigned g_bar_cnt;
__device__ unsigned g_bar_gen;

// ---------------- init (conv<0> must be 4th launch for ncu) ----------
__global__ void k_init_a(const float* __restrict__ codebook) {
    int i = blockIdx.x * blockDim.x + threadIdx.x;
    if (i < NS*NK*NE) { g_cb[i] = codebook[i]; g_ea[i] = codebook[i]; }
}
__global__ void k_init_b() {
    int i = blockIdx.x * blockDim.x + threadIdx.x;
    if (i < NS*NK) { g_csA[i] = 0.f; g_csB[i] = 0.f; }
    if (i < NB*64) g_h[i] = 0.f;
    if (i < NC) { g_bn1_sum[i]=0.f; g_bn1_sq[i]=0.f; g_bn2_sum[i]=0.f; g_bn2_sq[i]=0.f; }
    if (i == 0) { g_decl = 0.0; g_el = 0.0; g_bar_cnt = 0u; g_bar_gen = 0u; }
}
__global__ void k_init_cde() {
    int i = blockIdx.x * blockDim.x + threadIdx.x;
    if (i < NK) { g_cntA[i] = 0.f; g_cntB[i] = 0.f; }
    if (i < NK*NE) { g_sumA[i] = 0.f; g_sumB[i] = 0.f; }
}

// ---------------- fused conv: 3x3 SAME, 128->128, packed f32x2 FMAs --------
template<int MODE>
__global__ __launch_bounds__(128) void k_conv(
        const int* __restrict__ obs, const float* __restrict__ emb,
        const float* __restrict__ w, const float* __restrict__ bias,
        const float* __restrict__ bng, const float* __restrict__ bnb) {
    extern __shared__ float P[];                 // 128*108 floats
    int* sidx = (int*)(P + 128*108);             // 3*49 ints
    int n  = blockIdx.x;
    int co = threadIdx.x;

    #pragma unroll
    for (int q = 0; q < 108; q++) P[co*108 + q] = 0.f;

    if (MODE == 0) {
        int b = n >> 6, t = n & 63;
        for (int j = co; j < 3*HW; j += 128) {
            int pl = j / HW, pos = j % HW;
            sidx[j] = obs[(((b*65 + t)*3 + pl)*HW) + pos] + pl * 147;
        }
        __syncthreads();
        #pragma unroll 7
        for (int pos = 0; pos < HW; pos++) {
            float v = emb[sidx[pos]*NC + co]
                    + emb[sidx[HW + pos]*NC + co]
                    + emb[sidx[2*HW + pos]*NC + co];
            int h = pos / 7, wv = pos % 7;
            P[co*108 + (h+1)*12 + (wv+1)] = v;
        }
    } else {
        const float invN = 1.f / 200704.f;
        float m  = g_bn1_sum[co] * invN;
        float va = g_bn1_sq[co] * invN - m*m;
        float sc = bng[co] * rsqrtf(va + 1e-5f);
        float sh = bnb[co] - m * sc;
        const float* inp = g_X1 + (size_t)n * HW * NC;
        #pragma unroll 7
        for (int pos = 0; pos < HW; pos++) {
            float v = fmaxf(fmaf(inp[pos*NC + co], sc, sh), 0.f);
            int h = pos / 7, wv = pos % 7;
            P[co*108 + (h+1)*12 + (wv+1)] = v;
        }
        __syncthreads();
    }
    if (MODE == 0) __syncthreads();

    float bv = bias[co];
    ull  acc2[7][3];
    float accs[7];
    ull bvp = packf2(bv, bv);
    #pragma unroll
    for (int oh = 0; oh < 7; oh++) {
        accs[oh] = bv;
        #pragma unroll
        for (int j = 0; j < 3; j++) acc2[oh][j] = bvp;
    }

    for (int ci = 0; ci < NC; ci++) {
        float wt[9]; ull wp[9];
        #pragma unroll
        for (int tap = 0; tap < 9; tap++) {
            float wv = w[(tap*NC + ci)*NC + co];
            wt[tap] = wv; wp[tap] = packf2(wv, wv);
        }
        const float* rowp = &P[ci*108];
        #pragma unroll
        for (int r = 0; r < 9; r++) {
            float4 ra = *reinterpret_cast<const float4*>(rowp + r*12);
            float4 rb = *reinterpret_cast<const float4*>(rowp + r*12 + 4);
            float e8 = rowp[r*12 + 8];
            ull E0 = packf2(ra.x, ra.y), E1 = packf2(ra.z, ra.w);
            ull E2 = packf2(rb.x, rb.y), E3 = packf2(rb.z, rb.w);
            ull O0 = packf2(ra.y, ra.z), O1 = packf2(ra.w, rb.x);
            ull O2 = packf2(rb.y, rb.z);
            #pragma unroll
            for (int kh = 0; kh < 3; kh++) {
                int oh = r - kh;
                if (oh < 0 || oh > 6) continue;
                FFMA2(acc2[oh][0], E0, wp[kh*3+0]);
                FFMA2(acc2[oh][1], E1, wp[kh*3+0]);
                FFMA2(acc2[oh][2], E2, wp[kh*3+0]);
                accs[oh] = fmaf(rb.z, wt[kh*3+0], accs[oh]);
                FFMA2(acc2[oh][0], O0, wp[kh*3+1]);
                FFMA2(acc2[oh][1], O1, wp[kh*3+1]);
                FFMA2(acc2[oh][2], O2, wp[kh*3+1]);
                accs[oh] = fmaf(rb.w, wt[kh*3+1], accs[oh]);
                FFMA2(acc2[oh][0], E1, wp[kh*3+2]);
                FFMA2(acc2[oh][1], E2, wp[kh*3+2]);
                FFMA2(acc2[oh][2], E3, wp[kh*3+2]);
                accs[oh] = fmaf(e8, wt[kh*3+2], accs[oh]);
            }
        }
    }

    float s = 0.f, s2 = 0.f;
    float mx = -3.4e38f, mn = 3.4e38f;
    float* op = (MODE == 0) ? (g_X1 + (size_t)n * HW * NC) : (float*)0;
    #pragma unroll
    for (int oh = 0; oh < 7; oh++) {
        float v[7];
        unpackf2(acc2[oh][0], v[0], v[1]);
        unpackf2(acc2[oh][1], v[2], v[3]);
        unpackf2(acc2[oh][2], v[4], v[5]);
        v[6] = accs[oh];
        #pragma unroll
        for (int ow = 0; ow < 7; ow++) {
            float x = v[ow];
            s += x; s2 = fmaf(x, x, s2);
            if (MODE == 0) op[(oh*7 + ow)*NC + co] = x;
            else { mx = fmaxf(mx, x); mn = fminf(mn, x); }
        }
    }
    if (MODE == 0) {
        atomicAdd(&g_bn1_sum[co], s);
        atomicAdd(&g_bn1_sq[co], s2);
    } else {
        g_cmax[n*NC + co] = mx;
        g_cmin[n*NC + co] = mn;
        atomicAdd(&g_bn2_sum[co], s);
        atomicAdd(&g_bn2_sq[co], s2);
    }
}

// ---------------- bn2 + maxpool + relu -> obs_feat ----------------
__global__ void k_bn2max(const float* __restrict__ bng, const float* __restrict__ bnb) {
    int i = blockIdx.x * blockDim.x + threadIdx.x;
    if (i >= NIMG*NC) return;
    int c = i & 127;
    const float invN = 1.f / 200704.f;
    float m  = g_bn2_sum[c] * invN;
    float va = g_bn2_sq[c] * invN - m*m;
    float sc = bng[c] * rsqrtf(va + 1e-5f);
    float sh = bnb[c] - m * sc;
    float raw = (sc >= 0.f) ? g_cmax[i] : g_cmin[i];
    g_obs_feat[i] = fmaxf(fmaf(raw, sc, sh), 0.f);
}

// ---------------- gi = obs_feat @ Wih^T + bih ----------------
__global__ __launch_bounds__(192) void k_gi(const float* __restrict__ wih,
                                            const float* __restrict__ bih) {
    int n0 = blockIdx.x * 8;
    int j = threadIdx.x;
    __shared__ float xs[8*128];
    for (int i = j; i < 1024; i += 192) xs[i] = g_obs_feat[n0*128 + i];
    __syncthreads();
    float acc[8];
    float bv = bih[j];
    #pragma unroll
    for (int r = 0; r < 8; r++) acc[r] = bv;
    for (int i = 0; i < 128; i++) {
        float wv = wih[j*128 + i];
        #pragma unroll
        for (int r = 0; r < 8; r++) acc[r] = fmaf(xs[r*128 + i], wv, acc[r]);
    }
    #pragma unroll
    for (int r = 0; r < 8; r++) g_gi[(n0 + r)*192 + j] = acc[r];
}

// ---------------- GRU step 0 (h=0) + z(0) ----------------
__global__ __launch_bounds__(256) void k_gruz0(const float* __restrict__ bhh,
        const float* __restrict__ prew, const float* __restrict__ preb) {
    int b = blockIdx.x, tid = threadIdx.x;
    __shared__ float gh[192], hn[64];
    if (tid < 192) gh[tid] = bhh[tid];
    __syncthreads();
    if (tid < 64) {
        const float* gi = g_gi + (size_t)(b*64)*192;
        float zz = 1.f / (1.f + expf(-(gi[64 + tid] + gh[64 + tid])));
        float r  = 1.f / (1.f + expf(-(gi[tid] + gh[tid])));
        float nn = tanhf(gi[128 + tid] + r * gh[128 + tid]);
        float h = (1.f - zz) * nn;
        hn[tid] = h; g_h[b*64 + tid] = h;
    }
    __syncthreads();
    #pragma unroll
    for (int rep = 0; rep < 2; rep++) {
        int j = tid + rep*256;
        float a = preb[j];
        for (int i = 0; i < 64; i++) a = fmaf(hn[i], prew[i*512 + j], a);
        g_z[b*512 + j] = a;
    }
}

// ---------------- grid barrier (64 blocks, single wave guaranteed) --------
__device__ __forceinline__ void grid_barrier(unsigned &gen) {
    __syncthreads();
    if (threadIdx.x == 0) {
        __threadfence();
        unsigned arrived = atomicAdd(&g_bar_cnt, 1u);
        if (arrived == 63u) {
            atomicExch(&g_bar_cnt, 0u);
            __threadfence();
            atomicExch(&g_bar_gen, gen + 1u);
        } else {
            while (atomicAdd(&g_bar_gen, 0u) < gen + 1u) { __nanosleep(64); }
        }
        __threadfence();
    }
    gen++;
    __syncthreads();
}

// ---------------- persistent scan: 63 steps, 2 phases/step ----------------
// All cross-block data (z, pd, pi, cs, cb, cnt, sum) is accessed ONLY via
// __ldcg/__stcg/atomics inside this kernel (persistent L1 is not coherent).
__global__ __launch_bounds__(256) void k_scan(
        const float* __restrict__ m1w, const float* __restrict__ m1b,
        const float* __restrict__ m2w, const float* __restrict__ m2b,
        const float* __restrict__ whh, const float* __restrict__ bhh,
        const float* __restrict__ prew, const float* __restrict__ preb) {
    __shared__ float cbs[64*64];
    __shared__ float zsh[64*65];
    __shared__ float red[256];
    __shared__ float invc[64];
    __shared__ float pdl[4*64];
    __shared__ int   pil[4*64];
    __shared__ int   kmin[8];
    __shared__ float dmin[8];
    __shared__ float zq[512], h1[128], hs[64], gh[192], hn[64];

    unsigned gen = 0;
    int tid = threadIdx.x;

    for (int t = 0; t < NT; t++) {
        // ================= phase A: bid = (s, kc) =================
        {
            int s = blockIdx.x >> 3, kc = blockIdx.x & 7;
            const float* csr  = (t & 1) ? g_csB : g_csA;
            float*       csw  = (t & 1) ? g_csA : g_csB;
            const float* cntp = (t & 1) ? g_cntA : g_cntB;
            const float* sump = (t & 1) ? g_sumA : g_sumB;
            float*       cntc = (t & 1) ? g_cntB : g_cntA;
            float*       sumc = (t & 1) ? g_sumB : g_sumA;

            if (tid < 8) __stcg(&cntc[blockIdx.x*8 + tid], 0.f);
            if (tid < 128) __stcg(&reinterpret_cast<float4*>(sumc + blockIdx.x*512)[tid],
                                  make_float4(0.f,0.f,0.f,0.f));

            #pragma unroll
            for (int rep = 0; rep < 16; rep++) {
                int j = tid + rep*256;
                int bb = j >> 6, e = j & 63;
                zsh[e*65 + bb] = __ldcg(&g_z[bb*512 + s*64 + e]);
            }

            if (t > 0) {
                float c1 = fmaf(0.01f, __ldcg(&cntp[tid]),       __ldcg(&csr[s*NK + tid])       * 0.99f);
                float c2 = fmaf(0.01f, __ldcg(&cntp[tid + 256]), __ldcg(&csr[s*NK + tid + 256]) * 0.99f);
                red[tid] = c1 + c2;
                __syncthreads();
                for (int off = 128; off > 0; off >>= 1) {
                    if (tid < off) red[tid] += red[tid + off];
                    __syncthreads();
                }
                float ntot = red[0];
                if (tid < 64) {
                    int k = kc*64 + tid;
                    float cs_new = fmaf(0.01f, __ldcg(&cntp[k]), __ldcg(&csr[s*NK + k]) * 0.99f);
                    __stcg(&csw[s*NK + k], cs_new);
                    float csn = (cs_new + 1e-5f) / (ntot + 512.f * 1e-5f) * ntot;
                    invc[tid] = 1.f / csn;
                }
                __syncthreads();
                float4* ea4  = reinterpret_cast<float4*>(g_ea + ((size_t)s*NK + kc*64)*NE);
                float4* cbg4 = reinterpret_cast<float4*>(g_cb + ((size_t)s*NK + kc*64)*NE);
                const float4* sm4 = reinterpret_cast<const float4*>(sump + kc*64*NE);
                float4* cbs4 = reinterpret_cast<float4*>(cbs);
                #pragma unroll
                for (int rep = 0; rep < 4; rep++) {
                    int j = tid + rep*256;
                    float inv = invc[j >> 4];
                    float4 e = ea4[j];            // block-private: plain ld ok
                    float4 sv = __ldcg(&sm4[j]);
                    e.x = fmaf(0.01f, sv.x, e.x*0.99f);
                    e.y = fmaf(0.01f, sv.y, e.y*0.99f);
                    e.z = fmaf(0.01f, sv.z, e.z*0.99f);
                    e.w = fmaf(0.01f, sv.w, e.w*0.99f);
                    ea4[j] = e;
                    float4 cv = make_float4(e.x*inv, e.y*inv, e.z*inv, e.w*inv);
                    __stcg(&cbg4[j], cv);
                    cbs4[j] = cv;
                }
            } else {
                const float4* cbg4 = reinterpret_cast<const float4*>(g_cb + ((size_t)s*NK + kc*64)*NE);
                float4* cbs4 = reinterpret_cast<float4*>(cbs);
                #pragma unroll
                for (int rep = 0; rep < 4; rep++) cbs4[tid + rep*256] = __ldcg(&cbg4[tid + rep*256]);
            }
            __syncthreads();

            int b  = tid & 63;
            int kg = tid >> 6;
            float zreg[64];
            #pragma unroll
            for (int e = 0; e < 64; e++) zreg[e] = zsh[e*65 + b];
            float best = 3.4e38f; int bk = 0;
            #pragma unroll 4
            for (int j = 0; j < 16; j++) {
                int kl = kg*16 + j;
                const float4* row = reinterpret_cast<const float4*>(cbs + kl*64);
                float d = 0.f;
                #pragma unroll
                for (int e4 = 0; e4 < 16; e4++) {
                    float4 c = row[e4];
                    float dx = zreg[4*e4]   - c.x; d = fmaf(dx, dx, d);
                    dx = zreg[4*e4+1] - c.y; d = fmaf(dx, dx, d);
                    dx = zreg[4*e4+2] - c.z; d = fmaf(dx, dx, d);
                    dx = zreg[4*e4+3] - c.w; d = fmaf(dx, dx, d);
                }
                if (d < best) { best = d; bk = kl; }
            }
            pdl[kg*64 + b] = best; pil[kg*64 + b] = bk;
            __syncthreads();
            if (tid < 64) {
                float bd = pdl[tid]; int bi = pil[tid];
                #pragma unroll
                for (int g = 1; g < 4; g++) {
                    float d2 = pdl[g*64 + tid];
                    if (d2 < bd) { bd = d2; bi = pil[g*64 + tid]; }
                }
                __stcg(&g_pd[blockIdx.x*64 + tid], bd);
                __stcg(&g_pi[blockIdx.x*64 + tid], kc*64 + bi);
            }
        }
        grid_barrier(gen);

        // ================= phase B: bid = b =================
        {
            int b = blockIdx.x;
            float* cntc = (t & 1) ? g_cntB : g_cntA;
            float* sumc = (t & 1) ? g_sumB : g_sumA;

            if (tid < 64) hs[tid] = g_h[b*64 + tid];   // block-private
            if (tid < 8) {
                int s = tid;
                float bd = 3.4e38f; int bi = 0;
                #pragma unroll
                for (int kc = 0; kc < 8; kc++) {
                    float d = __ldcg(&g_pd[(s*8 + kc)*64 + b]);
                    if (d < bd) { bd = d; bi = __ldcg(&g_pi[(s*8 + kc)*64 + b]); }
                }
                kmin[s] = bi; dmin[s] = bd;
                atomicAdd(&cntc[bi], 1.0f);
            }
            __syncthreads();
            if (tid == 0) {
                double e = 0.0;
                #pragma unroll
                for (int s = 0; s < 8; s++) e += (double)dmin[s];
                atomicAdd(&g_el, e * (1.0 / 32768.0));
            }
            #pragma unroll
            for (int rep = 0; rep < 2; rep++) {
                int j = tid + rep*256;
                int s = j >> 6, e = j & 63;
                int k = kmin[s];
                zq[j] = __ldcg(&g_cb[((size_t)s*NK + k)*NE + e]);
                atomicAdd(&sumc[k*64 + e], __ldcg(&g_z[b*512 + j]));
            }
            __syncthreads();
            if (tid < 128) {
                float a = m1b[tid];
                for (int i = 0; i < 512; i += 4) {
                    float4 zv = *reinterpret_cast<const float4*>(&zq[i]);
                    a = fmaf(zv.x, m1w[i*128 + tid], a);
                    a = fmaf(zv.y, m1w[(i+1)*128 + tid], a);
                    a = fmaf(zv.z, m1w[(i+2)*128 + tid], a);
                    a = fmaf(zv.w, m1w[(i+3)*128 + tid], a);
                }
                h1[tid] = fmaxf(a, 0.f);
            }
            __syncthreads();
            {
                float a = m2b[tid];
                for (int i = 0; i < 128; i++) a = fmaf(h1[i], m2w[i*256 + tid], a);
                if (tid < 128) g_gab_g[((size_t)t*64 + b)*128 + tid] = 1.f + a;
                else           g_gab_b[((size_t)t*64 + b)*128 + (tid - 128)] = a;
            }
            if (t < 62) {
                __syncthreads();
                if (tid < 192) {
                    float a = bhh[tid];
                    for (int i = 0; i < 64; i++) a = fmaf(hs[i], whh[tid*64 + i], a);
                    gh[tid] = a;
                }
                __syncthreads();
                if (tid < 64) {
                    const float* gi = g_gi + ((size_t)(b*64 + t + 1))*192;
                    float r  = 1.f / (1.f + expf(-(gi[tid] + gh[tid])));
                    float zz = 1.f / (1.f + expf(-(gi[64 + tid] + gh[64 + tid])));
                    float nn = tanhf(gi[128 + tid] + r * gh[128 + tid]);
                    float h = (1.f - zz) * nn + zz * hs[tid];
                    hn[tid] = h; g_h[b*64 + tid] = h;
                }
                __syncthreads();
                #pragma unroll
                for (int rep = 0; rep < 2; rep++) {
                    int j = tid + rep*256;
                    float a = preb[j];
                    for (int i = 0; i < 64; i++) a = fmaf(hn[i], prew[i*512 + j], a);
                    __stcg(&g_z[b*512 + j], a);
                }
            }
        }
        grid_barrier(gen);
    }
}

// ---------------- batched decoder, 16 rows/block ----------------
__global__ __launch_bounds__(128) void k_dec(const int* __restrict__ acts,
        const float* __restrict__ w1, const float* __restrict__ b1,
        const float* __restrict__ w2, const float* __restrict__ b2,
        const float* __restrict__ w3, const float* __restrict__ b3) {
    int row0 = blockIdx.x * 16;
    int tp = row0 >> 6;
    int b0 = row0 & 63;
    float sq = sqrtf((float)(127*127 - 8*tp));
    int t = (int)((127.0f - sq) * 0.5f);
    while ((t+1)*(127-(t+1))/2 <= tp && t < 62) t++;
    while (t*(127-t)/2 > tp) t--;
    int p = t + (tp - t*(127-t)/2);
    int c = threadIdx.x;
    __shared__ float f[16][128];
    __shared__ float h1[16][128];
    __shared__ float h2[16][128];
    __shared__ float lg[16][6];
    __shared__ float ce[16];
    #pragma unroll
    for (int j = 0; j < 16; j++) {
        int b = b0 + j;
        float of = g_obs_feat[(b*64 + p)*NC + c];
        float fl = fmaf(of, g_gab_g[((size_t)t*64 + b)*128 + c],
                            g_gab_b[((size_t)t*64 + b)*128 + c]);
        f[j][c] = fmaxf(fl, 0.f);
    }
    __syncthreads();
    float acc[16];
    float bv = b1[c];
    #pragma unroll
    for (int j = 0; j < 16; j++) acc[j] = bv;
    for (int i = 0; i < 128; i += 4) {
        float wa = w1[i*128 + c], wb = w1[(i+1)*128 + c];
        float wc = w1[(i+2)*128 + c], wd = w1[(i+3)*128 + c];
        #pragma unroll
        for (int j = 0; j < 16; j++) {
            float4 fv = *reinterpret_cast<const float4*>(&f[j][i]);
            acc[j] = fmaf(fv.x, wa, fmaf(fv.y, wb, fmaf(fv.z, wc, fmaf(fv.w, wd, acc[j]))));
        }
    }
    #pragma unroll
    for (int j = 0; j < 16; j++) h1[j][c] = fmaxf(acc[j], 0.f);
    __syncthreads();
    bv = b2[c];
    #pragma unroll
    for (int j = 0; j < 16; j++) acc[j] = bv;
    for (int i = 0; i < 128; i += 4) {
        float wa = w2[i*128 + c], wb = w2[(i+1)*128 + c];
        float wc = w2[(i+2)*128 + c], wd = w2[(i+3)*128 + c];
        #pragma unroll
        for (int j = 0; j < 16; j++) {
            float4 fv = *reinterpret_cast<const float4*>(&h1[j][i]);
            acc[j] = fmaf(fv.x, wa, fmaf(fv.y, wb, fmaf(fv.z, wc, fmaf(fv.w, wd, acc[j]))));
        }
    }
    #pragma unroll
    for (int j = 0; j < 16; j++) h2[j][c] = fmaxf(acc[j], 0.f);
    __syncthreads();
    if (c < 96) {
        int j = c / 6, o = c % 6;
        float l = b3[o];
        for (int i = 0; i < 128; i++) l = fmaf(h2[j][i], w3[i*6 + o], l);
        lg[j][o] = l;
    }
    __syncthreads();
    if (c < 16) {
        int b = b0 + c;
        float m = lg[c][0];
        #pragma unroll
        for (int i = 1; i < 6; i++) m = fmaxf(m, lg[c][i]);
        float se = 0.f;
        #pragma unroll
        for (int i = 0; i < 6; i++) se += expf(lg[c][i] - m);
        float lse = m + logf(se);
        int a = acts[b*63 + p];
        ce[c] = lse - lg[c][a];
    }
    __syncthreads();
    if (c == 0) {
        double ssum = 0.0;
        #pragma unroll
        for (int j = 0; j < 16; j++) ssum += (double)ce[j];
        atomicAdd(&g_decl, ssum);
    }
}

// ---------------- finalize ----------------
__global__ void k_final(float* __restrict__ out) {
    if (threadIdx.x == 0) {
        out[0] = (float)(g_decl / 64.0);
        out[1] = (float)(g_el / 64.0);
    }
}

// ---------------- launch ----------------
extern "C" void kernel_launch(void* const* d_in, const int* in_sizes, int n_in,
                              void* d_out, int out_size) {
    const int*   obs  = (const int*)d_in[0];
    const int*   acts = (const int*)d_in[1];
    const float* emb  = (const float*)d_in[2];
    const float* c1w  = (const float*)d_in[3];
    const float* c1b  = (const float*)d_in[4];
    const float* bn1g = (const float*)d_in[5];
    const float* bn1b = (const float*)d_in[6];
    const float* c2w  = (const float*)d_in[7];
    const float* c2b  = (const float*)d_in[8];
    const float* bn2g = (const float*)d_in[9];
    const float* bn2b = (const float*)d_in[10];
    const float* wih  = (const float*)d_in[11];
    const float* whh  = (const float*)d_in[12];
    const float* bih  = (const float*)d_in[13];
    const float* bhh  = (const float*)d_in[14];
    const float* prew = (const float*)d_in[15];
    const float* preb = (const float*)d_in[16];
    const float* cbk  = (const float*)d_in[17];
    const float* m1w  = (const float*)d_in[18];
    const float* m1b  = (const float*)d_in[19];
    const float* m2w  = (const float*)d_in[20];
    const float* m2b  = (const float*)d_in[21];
    const float* d1w  = (const float*)d_in[22];
    const float* d1b  = (const float*)d_in[23];
    const float* d2w  = (const float*)d_in[24];
    const float* d2b  = (const float*)d_in[25];
    const float* d3w  = (const float*)d_in[26];
    const float* d3b  = (const float*)d_in[27];
    float* out = (float*)d_out;

    cudaFuncSetAttribute(k_conv<0>, cudaFuncAttributeMaxDynamicSharedMemorySize, CONV_SMEM);
    cudaFuncSetAttribute(k_conv<1>, cudaFuncAttributeMaxDynamicSharedMemorySize, CONV_SMEM);

    k_init_a<<<1024, 256>>>(cbk);
    k_init_b<<<16, 256>>>();
    k_init_cde<<<128, 256>>>();
    k_conv<0><<<NIMG, 128, CONV_SMEM>>>(obs, emb, c1w, c1b, (const float*)0, (const float*)0);  // 4th launch -> ncu
    k_conv<1><<<NIMG, 128, CONV_SMEM>>>(obs, emb, c2w, c2b, bn1g, bn1b);
    k_bn2max<<<(NIMG*NC + 255)/256, 256>>>(bn2g, bn2b);
    k_gi<<<NIMG/8, 192>>>(wih, bih);
    k_gruz0<<<NB, 256>>>(bhh, prew, preb);
    k_scan<<<64, 256>>>(m1w, m1b, m2w, m2b, whh, bhh, prew, preb);
    k_dec<<<129024/16, 128>>>(acts, d1w, d1b, d2w, d2b, d3w, d3b);
    k_final<<<1, 32>>>(out);
}

// round 8
// speedup vs baseline: 4.0388x; 1.1782x over previous
#include <cuda_runtime.h>
#include <math.h>

// Problem constants
#define NB    64
#define NIMG  4096    // NB*64
#define HW    49
#define NC    128
#define NS    8
#define NK    512
#define NE    64
#define NT    63

#define CONV_SMEM (128*108*4)

typedef unsigned long long ull;

__device__ __forceinline__ ull packf2(float lo, float hi) {
    ull d;
    asm("mov.b64 %0, {%1, %2};" : "=l"(d)
        : "r"(__float_as_uint(lo)), "r"(__float_as_uint(hi)));
    return d;
}
__device__ __forceinline__ void unpackf2(ull d, float& lo, float& hi) {
    unsigned int a, b;
    asm("mov.b64 {%0, %1}, %2;" : "=r"(a), "=r"(b) : "l"(d));
    lo = __uint_as_float(a); hi = __uint_as_float(b);
}
// (hi(x), lo(y)) as a pair
__device__ __forceinline__ ull mkpair(ull x, ull y) {
    ull r;
    asm("{ .reg .f32 a,b,c,d;\n\t"
        "mov.b64 {a,b}, %1;\n\t"
        "mov.b64 {c,d}, %2;\n\t"
        "mov.b64 %0, {b,c}; }"
        : "=l"(r) : "l"(x), "l"(y));
    return r;
}
__device__ __forceinline__ unsigned smem_u32(const void* p) {
    unsigned a;
    asm("{ .reg .u64 t; cvta.to.shared.u64 t, %1; cvt.u32.u64 %0, t; }"
        : "=r"(a) : "l"(p));
    return a;
}
#define FFMA2(d, a, b) asm("fma.rn.f32x2 %0, %1, %2, %0;" : "+l"(d) : "l"(a), "l"(b))

// ---------------- device scratch ----------------
__device__ float g_X1[NIMG*HW*NC];     // conv1 output (~98MB)
__device__ float g_EW[441*9*128];      // emb @ conv1_w table (2MB)
__device__ ull   g_wdup[9*128*128];    // conv2 weights duplicated (w,w)
__device__ float g_cmax[NIMG*NC];
__device__ float g_cmin[NIMG*NC];
__device__ float g_obs_feat[NIMG*NC];
__device__ float g_gi[NIMG*192];
__device__ float g_bn1_sum[NC];
__device__ float g_bn1_sq[NC];
__device__ float g_bn2_sum[NC];
__device__ float g_bn2_sq[NC];
__device__ float g_h[NB*64];
__device__ float g_z[NB*512];
__device__ float g_cb[NS*NK*NE];
__device__ float g_csA[NS*NK];
__device__ float g_csB[NS*NK];
__device__ float g_ea[NS*NK*NE];
__device__ float g_cntA[NK];
__device__ float g_cntB[NK];
__device__ float g_sumA[NK*NE];
__device__ float g_sumB[NK*NE];
__device__ float g_pd[64*64];
__device__ int   g_pi[64*64];
__device__ float g_gab_g[NT*NB*NC];
__device__ float g_gab_b[NT*NB*NC];
__device__ double g_decl;
__device__ double g_el;
__device__ unsigned g_bar_cnt;
__device__ unsigned g_bar_gen;

// ---------------- prep: duplicate conv2 weights + zero bn stats ----------
__global__ void k_wdup(const float* __restrict__ w2) {
    int i = blockIdx.x * blockDim.x + threadIdx.x;
    if (i < 9*128*128) { float v = w2[i]; g_wdup[i] = packf2(v, v); }
    if (i < NC) { g_bn1_sum[i]=0.f; g_bn1_sq[i]=0.f; g_bn2_sum[i]=0.f; g_bn2_sq[i]=0.f; }
}

// ---------------- EW[e][tap][co] = sum_ci emb[e][ci] * w1[tap][ci][co] ----
__global__ __launch_bounds__(128) void k_ew(const float* __restrict__ emb,
                                            const float* __restrict__ w1) {
    int e = blockIdx.x, co = threadIdx.x;
    __shared__ float es[128];
    es[co] = emb[e*128 + co];
    __syncthreads();
    #pragma unroll
    for (int tap = 0; tap < 9; tap++) {
        float a = 0.f;
        for (int ci = 0; ci < 128; ci++)
            a = fmaf(es[ci], w1[(tap*128 + ci)*128 + co], a);
        g_EW[(e*9 + tap)*128 + co] = a;
    }
}

// ---------------- conv1 via EW gather: out = b1 + sum taps/planes --------
__global__ __launch_bounds__(128) void k_conv1g(const int* __restrict__ obs,
                                                const float* __restrict__ b1) {
    int n = blockIdx.x, co = threadIdx.x;
    int b = n >> 6, t = n & 63;
    __shared__ int sidx[3*HW];           // (obs + plane*147) * 9, pre-scaled
    for (int j = co; j < 3*HW; j += 128) {
        int pl = j / HW, pos = j % HW;
        sidx[j] = (obs[(((b*65 + t)*3 + pl)*HW) + pos] + pl * 147) * 9;
    }
    __syncthreads();
    float bv = b1[co];
    float s = 0.f, s2 = 0.f;
    float* op = g_X1 + (size_t)n * HW * NC;
    for (int oh = 0; oh < 7; oh++) {
        for (int ow = 0; ow < 7; ow++) {
            float a = bv;
            #pragma unroll
            for (int kh = 0; kh < 3; kh++) {
                int ih = oh + kh - 1;
                if (ih < 0 || ih > 6) continue;
                #pragma unroll
                for (int kw = 0; kw < 3; kw++) {
                    int iw = ow + kw - 1;
                    if (iw < 0 || iw > 6) continue;
                    int q = ih*7 + iw, tap = kh*3 + kw;
                    a += __ldg(&g_EW[(sidx[q]      + tap)*128 + co])
                       + __ldg(&g_EW[(sidx[HW + q] + tap)*128 + co])
                       + __ldg(&g_EW[(sidx[2*HW+q] + tap)*128 + co]);
                }
            }
            op[(oh*7 + ow)*NC + co] = a;
            s += a; s2 = fmaf(a, a, s2);
        }
    }
    atomicAdd(&g_bn1_sum[co], s);
    atomicAdd(&g_bn1_sq[co], s2);
}

// ---------------- conv2: 3x3 SAME, 128->128, pack-free FFMA2 --------------
// input = bn1-applied relu of g_X1; output -> per-image min/max + bn2 stats.
__global__ __launch_bounds__(128) void k_conv2(
        const float* __restrict__ bias,
        const float* __restrict__ bng, const float* __restrict__ bnb) {
    extern __shared__ float P[];                 // 128*108 floats
    int n  = blockIdx.x;
    int co = threadIdx.x;

    const float invN = 1.f / 200704.f;
    float m  = g_bn1_sum[co] * invN;
    float va = g_bn1_sq[co] * invN - m*m;
    float sc = bng[co] * rsqrtf(va + 1e-5f);
    float sh = bnb[co] - m * sc;

    #pragma unroll
    for (int q = 0; q < 108; q++) P[co*108 + q] = 0.f;
    const float* inp = g_X1 + (size_t)n * HW * NC;
    #pragma unroll 7
    for (int pos = 0; pos < HW; pos++) {
        float v = fmaxf(fmaf(inp[pos*NC + co], sc, sh), 0.f);
        int h = pos / 7, wv = pos % 7;
        P[co*108 + (h+1)*12 + (wv+1)] = v;
    }
    __syncthreads();

    unsigned pbase = smem_u32(P);
    float bv = bias[co];
    ull bp = packf2(bv, bv);
    ull acc[7][4];
    #pragma unroll
    for (int oh = 0; oh < 7; oh++) {
        #pragma unroll
        for (int j = 0; j < 4; j++) acc[oh][j] = bp;
    }

    for (int ci = 0; ci < NC; ci++) {
        ull wp[9];
        #pragma unroll
        for (int tap = 0; tap < 9; tap++)
            wp[tap] = g_wdup[(tap*NC + ci)*NC + co];
        unsigned rb = pbase + ci*432;
        #pragma unroll
        for (int r = 0; r < 9; r++) {
            ull E0, E1, E2, E3, P8;
            unsigned a0 = rb + r*48;
            asm volatile("ld.shared.v2.b64 {%0,%1},[%2];" : "=l"(E0), "=l"(E1) : "r"(a0));
            asm volatile("ld.shared.v2.b64 {%0,%1},[%2];" : "=l"(E2), "=l"(E3) : "r"(a0 + 16));
            asm volatile("ld.shared.b64 %0,[%1];" : "=l"(P8) : "r"(a0 + 32));
            ull O0 = mkpair(E0, E1);   // (c1,c2)
            ull O1 = mkpair(E1, E2);   // (c3,c4)
            ull O2 = mkpair(E2, E3);   // (c5,c6)
            ull O3 = mkpair(E3, P8);   // (c7,c8)
            #pragma unroll
            for (int kh = 0; kh < 3; kh++) {
                int oh = r - kh;
                if (oh < 0 || oh > 6) continue;
                ull w0 = wp[kh*3+0], w1_ = wp[kh*3+1], w2_ = wp[kh*3+2];
                FFMA2(acc[oh][0], E0, w0);  FFMA2(acc[oh][1], E1, w0);
                FFMA2(acc[oh][2], E2, w0);  FFMA2(acc[oh][3], E3, w0);
                FFMA2(acc[oh][0], O0, w1_); FFMA2(acc[oh][1], O1, w1_);
                FFMA2(acc[oh][2], O2, w1_); FFMA2(acc[oh][3], O3, w1_);
                FFMA2(acc[oh][0], E1, w2_); FFMA2(acc[oh][1], E2, w2_);
                FFMA2(acc[oh][2], E3, w2_); FFMA2(acc[oh][3], P8, w2_);
            }
        }
    }

    float s = 0.f, s2 = 0.f;
    float mx = -3.4e38f, mn = 3.4e38f;
    #pragma unroll
    for (int oh = 0; oh < 7; oh++) {
        float v[8];
        unpackf2(acc[oh][0], v[0], v[1]);
        unpackf2(acc[oh][1], v[2], v[3]);
        unpackf2(acc[oh][2], v[4], v[5]);
        unpackf2(acc[oh][3], v[6], v[7]);     // v[7] = junk lane
        #pragma unroll
        for (int ow = 0; ow < 7; ow++) {
            float x = v[ow];
            s += x; s2 = fmaf(x, x, s2);
            mx = fmaxf(mx, x); mn = fminf(mn, x);
        }
    }
    g_cmax[n*NC + co] = mx;
    g_cmin[n*NC + co] = mn;
    atomicAdd(&g_bn2_sum[co], s);
    atomicAdd(&g_bn2_sq[co], s2);
}

// ---------------- init ----------------
__global__ void k_init_a(const float* __restrict__ codebook) {
    int i = blockIdx.x * blockDim.x + threadIdx.x;
    if (i < NS*NK*NE) { g_cb[i] = codebook[i]; g_ea[i] = codebook[i]; }
}
__global__ void k_init_b() {
    int i = blockIdx.x * blockDim.x + threadIdx.x;
    if (i < NS*NK) { g_csA[i] = 0.f; g_csB[i] = 0.f; }
    if (i < NB*64) g_h[i] = 0.f;
    if (i == 0) { g_decl = 0.0; g_el = 0.0; g_bar_cnt = 0u; g_bar_gen = 0u; }
}
__global__ void k_init_cde() {
    int i = blockIdx.x * blockDim.x + threadIdx.x;
    if (i < NK) { g_cntA[i] = 0.f; g_cntB[i] = 0.f; }
    if (i < NK*NE) { g_sumA[i] = 0.f; g_sumB[i] = 0.f; }
}

// ---------------- bn2 + maxpool + relu -> obs_feat ----------------
__global__ void k_bn2max(const float* __restrict__ bng, const float* __restrict__ bnb) {
    int i = blockIdx.x * blockDim.x + threadIdx.x;
    if (i >= NIMG*NC) return;
    int c = i & 127;
    const float invN = 1.f / 200704.f;
    float m  = g_bn2_sum[c] * invN;
    float va = g_bn2_sq[c] * invN - m*m;
    float sc = bng[c] * rsqrtf(va + 1e-5f);
    float sh = bnb[c] - m * sc;
    float raw = (sc >= 0.f) ? g_cmax[i] : g_cmin[i];
    g_obs_feat[i] = fmaxf(fmaf(raw, sc, sh), 0.f);
}

// ---------------- gi = obs_feat @ Wih^T + bih ----------------
__global__ __launch_bounds__(192) void k_gi(const float* __restrict__ wih,
                                            const float* __restrict__ bih) {
    int n0 = blockIdx.x * 8;
    int j = threadIdx.x;
    __shared__ float xs[8*128];
    for (int i = j; i < 1024; i += 192) xs[i] = g_obs_feat[n0*128 + i];
    __syncthreads();
    float acc[8];
    float bv = bih[j];
    #pragma unroll
    for (int r = 0; r < 8; r++) acc[r] = bv;
    for (int i = 0; i < 128; i++) {
        float wv = wih[j*128 + i];
        #pragma unroll
        for (int r = 0; r < 8; r++) acc[r] = fmaf(xs[r*128 + i], wv, acc[r]);
    }
    #pragma unroll
    for (int r = 0; r < 8; r++) g_gi[(n0 + r)*192 + j] = acc[r];
}

// ---------------- GRU step 0 (h=0) + z(0) ----------------
__global__ __launch_bounds__(256) void k_gruz0(const float* __restrict__ bhh,
        const float* __restrict__ prew, const float* __restrict__ preb) {
    int b = blockIdx.x, tid = threadIdx.x;
    __shared__ float gh[192], hn[64];
    if (tid < 192) gh[tid] = bhh[tid];
    __syncthreads();
    if (tid < 64) {
        const float* gi = g_gi + (size_t)(b*64)*192;
        float zz = 1.f / (1.f + expf(-(gi[64 + tid] + gh[64 + tid])));
        float r  = 1.f / (1.f + expf(-(gi[tid] + gh[tid])));
        float nn = tanhf(gi[128 + tid] + r * gh[128 + tid]);
        float h = (1.f - zz) * nn;
        hn[tid] = h; g_h[b*64 + tid] = h;
    }
    __syncthreads();
    #pragma unroll
    for (int rep = 0; rep < 2; rep++) {
        int j = tid + rep*256;
        float a = preb[j];
        for (int i = 0; i < 64; i++) a = fmaf(hn[i], prew[i*512 + j], a);
        g_z[b*512 + j] = a;
    }
}

// ---------------- grid barrier (64 blocks, single wave guaranteed) --------
__device__ __forceinline__ void grid_barrier(unsigned &gen) {
    __syncthreads();
    if (threadIdx.x == 0) {
        __threadfence();
        unsigned arrived = atomicAdd(&g_bar_cnt, 1u);
        if (arrived == 63u) {
            atomicExch(&g_bar_cnt, 0u);
            __threadfence();
            atomicExch(&g_bar_gen, gen + 1u);
        } else {
            while (atomicAdd(&g_bar_gen, 0u) < gen + 1u) { __nanosleep(64); }
        }
        __threadfence();
    }
    gen++;
    __syncthreads();
}

// ---------------- persistent scan: 63 steps, 2 phases/step ----------------
__global__ __launch_bounds__(256) void k_scan(
        const float* __restrict__ m1w, const float* __restrict__ m1b,
        const float* __restrict__ m2w, const float* __restrict__ m2b,
        const float* __restrict__ whh, const float* __restrict__ bhh,
        const float* __restrict__ prew, const float* __restrict__ preb) {
    __shared__ float cbs[64*64];
    __shared__ float zsh[64*65];
    __shared__ float red[256];
    __shared__ float invc[64];
    __shared__ float pdl[4*64];
    __shared__ int   pil[4*64];
    __shared__ int   kmin[8];
    __shared__ float dmin[8];
    __shared__ float zq[512], h1[128], hs[64], gh[192], hn[64];

    unsigned gen = 0;
    int tid = threadIdx.x;

    for (int t = 0; t < NT; t++) {
        // ================= phase A: bid = (s, kc) =================
        {
            int s = blockIdx.x >> 3, kc = blockIdx.x & 7;
            const float* csr  = (t & 1) ? g_csB : g_csA;
            float*       csw  = (t & 1) ? g_csA : g_csB;
            const float* cntp = (t & 1) ? g_cntA : g_cntB;
            const float* sump = (t & 1) ? g_sumA : g_sumB;
            float*       cntc = (t & 1) ? g_cntB : g_cntA;
            float*       sumc = (t & 1) ? g_sumB : g_sumA;

            if (tid < 8) __stcg(&cntc[blockIdx.x*8 + tid], 0.f);
            if (tid < 128) __stcg(&reinterpret_cast<float4*>(sumc + blockIdx.x*512)[tid],
                                  make_float4(0.f,0.f,0.f,0.f));

            #pragma unroll
            for (int rep = 0; rep < 16; rep++) {
                int j = tid + rep*256;
                int bb = j >> 6, e = j & 63;
                zsh[e*65 + bb] = __ldcg(&g_z[bb*512 + s*64 + e]);
            }

            if (t > 0) {
                float c1 = fmaf(0.01f, __ldcg(&cntp[tid]),       __ldcg(&csr[s*NK + tid])       * 0.99f);
                float c2 = fmaf(0.01f, __ldcg(&cntp[tid + 256]), __ldcg(&csr[s*NK + tid + 256]) * 0.99f);
                red[tid] = c1 + c2;
                __syncthreads();
                for (int off = 128; off > 0; off >>= 1) {
                    if (tid < off) red[tid] += red[tid + off];
                    __syncthreads();
                }
                float ntot = red[0];
                if (tid < 64) {
                    int k = kc*64 + tid;
                    float cs_new = fmaf(0.01f, __ldcg(&cntp[k]), __ldcg(&csr[s*NK + k]) * 0.99f);
                    __stcg(&csw[s*NK + k], cs_new);
                    float csn = (cs_new + 1e-5f) / (ntot + 512.f * 1e-5f) * ntot;
                    invc[tid] = 1.f / csn;
                }
                __syncthreads();
                float4* ea4  = reinterpret_cast<float4*>(g_ea + ((size_t)s*NK + kc*64)*NE);
                float4* cbg4 = reinterpret_cast<float4*>(g_cb + ((size_t)s*NK + kc*64)*NE);
                const float4* sm4 = reinterpret_cast<const float4*>(sump + kc*64*NE);
                float4* cbs4 = reinterpret_cast<float4*>(cbs);
                #pragma unroll
                for (int rep = 0; rep < 4; rep++) {
                    int j = tid + rep*256;
                    float inv = invc[j >> 4];
                    float4 e = ea4[j];            // block-private
                    float4 sv = __ldcg(&sm4[j]);
                    e.x = fmaf(0.01f, sv.x, e.x*0.99f);
                    e.y = fmaf(0.01f, sv.y, e.y*0.99f);
                    e.z = fmaf(0.01f, sv.z, e.z*0.99f);
                    e.w = fmaf(0.01f, sv.w, e.w*0.99f);
                    ea4[j] = e;
                    float4 cv = make_float4(e.x*inv, e.y*inv, e.z*inv, e.w*inv);
                    __stcg(&cbg4[j], cv);
                    cbs4[j] = cv;
                }
            } else {
                const float4* cbg4 = reinterpret_cast<const float4*>(g_cb + ((size_t)s*NK + kc*64)*NE);
                float4* cbs4 = reinterpret_cast<float4*>(cbs);
                #pragma unroll
                for (int rep = 0; rep < 4; rep++) cbs4[tid + rep*256] = __ldcg(&cbg4[tid + rep*256]);
            }
            __syncthreads();

            int b  = tid & 63;
            int kg = tid >> 6;
            float zreg[64];
            #pragma unroll
            for (int e = 0; e < 64; e++) zreg[e] = zsh[e*65 + b];
            float best = 3.4e38f; int bk = 0;
            #pragma unroll 4
            for (int j = 0; j < 16; j++) {
                int kl = kg*16 + j;
                const float4* row = reinterpret_cast<const float4*>(cbs + kl*64);
                float d = 0.f;
                #pragma unroll
                for (int e4 = 0; e4 < 16; e4++) {
                    float4 c = row[e4];
                    float dx = zreg[4*e4]   - c.x; d = fmaf(dx, dx, d);
                    dx = zreg[4*e4+1] - c.y; d = fmaf(dx, dx, d);
                    dx = zreg[4*e4+2] - c.z; d = fmaf(dx, dx, d);
                    dx = zreg[4*e4+3] - c.w; d = fmaf(dx, dx, d);
                }
                if (d < best) { best = d; bk = kl; }
            }
            pdl[kg*64 + b] = best; pil[kg*64 + b] = bk;
            __syncthreads();
            if (tid < 64) {
                float bd = pdl[tid]; int bi = pil[tid];
                #pragma unroll
                for (int g = 1; g < 4; g++) {
                    float d2 = pdl[g*64 + tid];
                    if (d2 < bd) { bd = d2; bi = pil[g*64 + tid]; }
                }
                __stcg(&g_pd[blockIdx.x*64 + tid], bd);
                __stcg(&g_pi[blockIdx.x*64 + tid], kc*64 + bi);
            }
        }
        grid_barrier(gen);

        // ================= phase B: bid = b =================
        {
            int b = blockIdx.x;
            float* cntc = (t & 1) ? g_cntB : g_cntA;
            float* sumc = (t & 1) ? g_sumB : g_sumA;

            if (tid < 64) hs[tid] = g_h[b*64 + tid];
            if (tid < 8) {
                int s = tid;
                float bd = 3.4e38f; int bi = 0;
                #pragma unroll
                for (int kc = 0; kc < 8; kc++) {
                    float d = __ldcg(&g_pd[(s*8 + kc)*64 + b]);
                    if (d < bd) { bd = d; bi = __ldcg(&g_pi[(s*8 + kc)*64 + b]); }
                }
                kmin[s] = bi; dmin[s] = bd;
                atomicAdd(&cntc[bi], 1.0f);
            }
            __syncthreads();
            if (tid == 0) {
                double e = 0.0;
                #pragma unroll
                for (int s = 0; s < 8; s++) e += (double)dmin[s];
                atomicAdd(&g_el, e * (1.0 / 32768.0));
            }
            #pragma unroll
            for (int rep = 0; rep < 2; rep++) {
                int j = tid + rep*256;
                int s = j >> 6, e = j & 63;
                int k = kmin[s];
                zq[j] = __ldcg(&g_cb[((size_t)s*NK + k)*NE + e]);
                atomicAdd(&sumc[k*64 + e], __ldcg(&g_z[b*512 + j]));
            }
            __syncthreads();
            if (tid < 128) {
                float a = m1b[tid];
                for (int i = 0; i < 512; i += 4) {
                    float4 zv = *reinterpret_cast<const float4*>(&zq[i]);
                    a = fmaf(zv.x, m1w[i*128 + tid], a);
                    a = fmaf(zv.y, m1w[(i+1)*128 + tid], a);
                    a = fmaf(zv.z, m1w[(i+2)*128 + tid], a);
                    a = fmaf(zv.w, m1w[(i+3)*128 + tid], a);
                }
                h1[tid] = fmaxf(a, 0.f);
            }
            __syncthreads();
            {
                float a = m2b[tid];
                for (int i = 0; i < 128; i++) a = fmaf(h1[i], m2w[i*256 + tid], a);
                if (tid < 128) g_gab_g[((size_t)t*64 + b)*128 + tid] = 1.f + a;
                else           g_gab_b[((size_t)t*64 + b)*128 + (tid - 128)] = a;
            }
            if (t < 62) {
                __syncthreads();
                if (tid < 192) {
                    float a = bhh[tid];
                    for (int i = 0; i < 64; i++) a = fmaf(hs[i], whh[tid*64 + i], a);
                    gh[tid] = a;
                }
                __syncthreads();
                if (tid < 64) {
                    const float* gi = g_gi + ((size_t)(b*64 + t + 1))*192;
                    float r  = 1.f / (1.f + expf(-(gi[tid] + gh[tid])));
                    float zz = 1.f / (1.f + expf(-(gi[64 + tid] + gh[64 + tid])));
                    float nn = tanhf(gi[128 + tid] + r * gh[128 + tid]);
                    float h = (1.f - zz) * nn + zz * hs[tid];
                    hn[tid] = h; g_h[b*64 + tid] = h;
                }
                __syncthreads();
                #pragma unroll
                for (int rep = 0; rep < 2; rep++) {
                    int j = tid + rep*256;
                    float a = preb[j];
                    for (int i = 0; i < 64; i++) a = fmaf(hn[i], prew[i*512 + j], a);
                    __stcg(&g_z[b*512 + j], a);
                }
            }
        }
        grid_barrier(gen);
    }
}

// ---------------- batched decoder, 16 rows/block ----------------
__global__ __launch_bounds__(128) void k_dec(const int* __restrict__ acts,
        const float* __restrict__ w1, const float* __restrict__ b1,
        const float* __restrict__ w2, const float* __restrict__ b2,
        const float* __restrict__ w3, const float* __restrict__ b3) {
    int row0 = blockIdx.x * 16;
    int tp = row0 >> 6;
    int b0 = row0 & 63;
    float sq = sqrtf((float)(127*127 - 8*tp));
    int t = (int)((127.0f - sq) * 0.5f);
    while ((t+1)*(127-(t+1))/2 <= tp && t < 62) t++;
    while (t*(127-t)/2 > tp) t--;
    int p = t + (tp - t*(127-t)/2);
    int c = threadIdx.x;
    __shared__ float f[16][128];
    __shared__ float h1[16][128];
    __shared__ float h2[16][128];
    __shared__ float lg[16][6];
    __shared__ float ce[16];
    #pragma unroll
    for (int j = 0; j < 16; j++) {
        int b = b0 + j;
        float of = g_obs_feat[(b*64 + p)*NC + c];
        float fl = fmaf(of, g_gab_g[((size_t)t*64 + b)*128 + c],
                            g_gab_b[((size_t)t*64 + b)*128 + c]);
        f[j][c] = fmaxf(fl, 0.f);
    }
    __syncthreads();
    float acc[16];
    float bv = b1[c];
    #pragma unroll
    for (int j = 0; j < 16; j++) acc[j] = bv;
    for (int i = 0; i < 128; i += 4) {
        float wa = w1[i*128 + c], wb = w1[(i+1)*128 + c];
        float wc = w1[(i+2)*128 + c], wd = w1[(i+3)*128 + c];
        #pragma unroll
        for (int j = 0; j < 16; j++) {
            float4 fv = *reinterpret_cast<const float4*>(&f[j][i]);
            acc[j] = fmaf(fv.x, wa, fmaf(fv.y, wb, fmaf(fv.z, wc, fmaf(fv.w, wd, acc[j]))));
        }
    }
    #pragma unroll
    for (int j = 0; j < 16; j++) h1[j][c] = fmaxf(acc[j], 0.f);
    __syncthreads();
    bv = b2[c];
    #pragma unroll
    for (int j = 0; j < 16; j++) acc[j] = bv;
    for (int i = 0; i < 128; i += 4) {
        float wa = w2[i*128 + c], wb = w2[(i+1)*128 + c];
        float wc = w2[(i+2)*128 + c], wd = w2[(i+3)*128 + c];
        #pragma unroll
        for (int j = 0; j < 16; j++) {
            float4 fv = *reinterpret_cast<const float4*>(&h1[j][i]);
            acc[j] = fmaf(fv.x, wa, fmaf(fv.y, wb, fmaf(fv.z, wc, fmaf(fv.w, wd, acc[j]))));
        }
    }
    #pragma unroll
    for (int j = 0; j < 16; j++) h2[j][c] = fmaxf(acc[j], 0.f);
    __syncthreads();
    if (c < 96) {
        int j = c / 6, o = c % 6;
        float l = b3[o];
        for (int i = 0; i < 128; i++) l = fmaf(h2[j][i], w3[i*6 + o], l);
        lg[j][o] = l;
    }
    __syncthreads();
    if (c < 16) {
        int b = b0 + c;
        float m = lg[c][0];
        #pragma unroll
        for (int i = 1; i < 6; i++) m = fmaxf(m, lg[c][i]);
        float se = 0.f;
        #pragma unroll
        for (int i = 0; i < 6; i++) se += expf(lg[c][i] - m);
        float lse = m + logf(se);
        int a = acts[b*63 + p];
        ce[c] = lse - lg[c][a];
    }
    __syncthreads();
    if (c == 0) {
        double ssum = 0.0;
        #pragma unroll
        for (int j = 0; j < 16; j++) ssum += (double)ce[j];
        atomicAdd(&g_decl, ssum);
    }
}

// ---------------- finalize ----------------
__global__ void k_final(float* __restrict__ out) {
    if (threadIdx.x == 0) {
        out[0] = (float)(g_decl / 64.0);
        out[1] = (float)(g_el / 64.0);
    }
}

// ---------------- launch ----------------
extern "C" void kernel_launch(void* const* d_in, const int* in_sizes, int n_in,
                              void* d_out, int out_size) {
    const int*   obs  = (const int*)d_in[0];
    const int*   acts = (const int*)d_in[1];
    const float* emb  = (const float*)d_in[2];
    const float* c1w  = (const float*)d_in[3];
    const float* c1b  = (const float*)d_in[4];
    const float* bn1g = (const float*)d_in[5];
    const float* bn1b = (const float*)d_in[6];
    const float* c2w  = (const float*)d_in[7];
    const float* c2b  = (const float*)d_in[8];
    const float* bn2g = (const float*)d_in[9];
    const float* bn2b = (const float*)d_in[10];
    const float* wih  = (const float*)d_in[11];
    const float* whh  = (const float*)d_in[12];
    const float* bih  = (const float*)d_in[13];
    const float* bhh  = (const float*)d_in[14];
    const float* prew = (const float*)d_in[15];
    const float* preb = (const float*)d_in[16];
    const float* cbk  = (const float*)d_in[17];
    const float* m1w  = (const float*)d_in[18];
    const float* m1b  = (const float*)d_in[19];
    const float* m2w  = (const float*)d_in[20];
    const float* m2b  = (const float*)d_in[21];
    const float* d1w  = (const float*)d_in[22];
    const float* d1b  = (const float*)d_in[23];
    const float* d2w  = (const float*)d_in[24];
    const float* d2b  = (const float*)d_in[25];
    const float* d3w  = (const float*)d_in[26];
    const float* d3b  = (const float*)d_in[27];
    float* out = (float*)d_out;

    cudaFuncSetAttribute(k_conv2, cudaFuncAttributeMaxDynamicSharedMemorySize, CONV_SMEM);

    k_wdup<<<576, 256>>>(c2w);                                   // 1: dup w2 + zero bn stats
    k_ew<<<441, 128>>>(emb, c1w);                                // 2: EW table
    k_conv1g<<<NIMG, 128>>>(obs, c1b);                           // 3: conv1 gather + bn1 stats
    k_conv2<<<NIMG, 128, CONV_SMEM>>>(c2b, bn2g, bn2b);          // 4: conv2 (ncu slot)
    k_init_a<<<1024, 256>>>(cbk);
    k_init_b<<<16, 256>>>();
    k_init_cde<<<128, 256>>>();
    k_bn2max<<<(NIMG*NC + 255)/256, 256>>>(bn2g, bn2b);
    k_gi<<<NIMG/8, 192>>>(wih, bih);
    k_gruz0<<<NB, 256>>>(bhh, prew, preb);
    k_scan<<<64, 256>>>(m1w, m1b, m2w, m2b, whh, bhh, prew, preb);
    k_dec<<<129024/16, 128>>>(acts, d1w, d1b, d2w, d2b, d3w, d3b);
    k_final<<<1, 32>>>(out);
}

// round 10
// speedup vs baseline: 4.3324x; 1.0727x over previous
#include <cuda_runtime.h>
#include <math.h>

// Problem constants
#define NB    64
#define NIMG  4096    // NB*64
#define HW    49
#define NC    128
#define NS    8
#define NK    512
#define NE    64
#define NT    63

#define CONV_SMEM (128*108*4)

typedef unsigned long long ull;

__device__ __forceinline__ ull packf2(float lo, float hi) {
    ull d;
    asm("mov.b64 %0, {%1, %2};" : "=l"(d)
        : "r"(__float_as_uint(lo)), "r"(__float_as_uint(hi)));
    return d;
}
__device__ __forceinline__ void unpackf2(ull d, float& lo, float& hi) {
    unsigned int a, b;
    asm("mov.b64 {%0, %1}, %2;" : "=r"(a), "=r"(b) : "l"(d));
    lo = __uint_as_float(a); hi = __uint_as_float(b);
}
__device__ __forceinline__ unsigned smem_u32(const void* p) {
    unsigned a;
    asm("{ .reg .u64 t; cvta.to.shared.u64 t, %1; cvt.u32.u64 %0, t; }"
        : "=r"(a) : "l"(p));
    return a;
}
#define FFMA2(d, a, b) asm("fma.rn.f32x2 %0, %1, %2, %0;" : "+l"(d) : "l"(a), "l"(b))

// ---------------- device scratch ----------------
__device__ float g_X1[NIMG*HW*NC];     // conv1 output (~98MB)
__device__ float g_EW[441*9*128];      // emb @ conv1_w table (2MB)
__device__ ull   g_wdup[9*128*128];    // conv2 weights duplicated (w,w)
__device__ float g_cmax[NIMG*NC];
__device__ float g_cmin[NIMG*NC];
__device__ float g_obs_feat[NIMG*NC];
__device__ float g_gi[NIMG*192];
__device__ float g_bn1_sum[NC];
__device__ float g_bn1_sq[NC];
__device__ float g_bn2_sum[NC];
__device__ float g_bn2_sq[NC];
__device__ float g_h[NB*64];
__device__ float g_z[NB*512];
__device__ float g_cb[NS*NK*NE];
__device__ float g_csA[NS*NK];
__device__ float g_csB[NS*NK];
__device__ float g_ea[NS*NK*NE];
__device__ float g_cntA[NK];
__device__ float g_cntB[NK];
__device__ float g_sumA[NK*NE];
__device__ float g_sumB[NK*NE];
__device__ float g_pd[64*64];
__device__ int   g_pi[64*64];
__device__ float g_gab_g[NT*NB*NC];
__device__ float g_gab_b[NT*NB*NC];
__device__ double g_decl;
__device__ double g_el;
__device__ unsigned g_bar_cnt;
__device__ unsigned g_bar_gen;

// ---------------- prep: duplicate conv2 weights + zero bn stats ----------
__global__ void k_wdup(const float* __restrict__ w2) {
    int i = blockIdx.x * blockDim.x + threadIdx.x;
    if (i < 9*128*128) { float v = w2[i]; g_wdup[i] = packf2(v, v); }
    if (i < NC) { g_bn1_sum[i]=0.f; g_bn1_sq[i]=0.f; g_bn2_sum[i]=0.f; g_bn2_sq[i]=0.f; }
}

// ---------------- EW[e][tap][co] = sum_ci emb[e][ci] * w1[tap][ci][co] ----
__global__ __launch_bounds__(128) void k_ew(const float* __restrict__ emb,
                                            const float* __restrict__ w1) {
    int e = blockIdx.x, co = threadIdx.x;
    __shared__ float es[128];
    es[co] = emb[e*128 + co];
    __syncthreads();
    #pragma unroll
    for (int tap = 0; tap < 9; tap++) {
        float a = 0.f;
        for (int ci = 0; ci < 128; ci++)
            a = fmaf(es[ci], w1[(tap*128 + ci)*128 + co], a);
        g_EW[(e*9 + tap)*128 + co] = a;
    }
}

// ---------------- conv1 via EW gather, 256 thr: rows 0-3 / 4-6 split -----
__global__ __launch_bounds__(256) void k_conv1g(const int* __restrict__ obs,
                                                const float* __restrict__ b1) {
    int n = blockIdx.x;
    int co = threadIdx.x & 127, grp = threadIdx.x >> 7;
    int b = n >> 6, t = n & 63;
    __shared__ int sidx[3*HW];           // (obs + plane*147) * 9, pre-scaled
    for (int j = threadIdx.x; j < 3*HW; j += 256) {
        int pl = j / HW, pos = j % HW;
        sidx[j] = (obs[(((b*65 + t)*3 + pl)*HW) + pos] + pl * 147) * 9;
    }
    __syncthreads();
    float bv = b1[co];
    float s = 0.f, s2 = 0.f;
    float* op = g_X1 + (size_t)n * HW * NC;
    int oh0 = grp ? 4 : 0, oh1 = grp ? 7 : 4;
    for (int oh = oh0; oh < oh1; oh++) {
        for (int ow = 0; ow < 7; ow++) {
            float a = bv;
            #pragma unroll
            for (int kh = 0; kh < 3; kh++) {
                int ih = oh + kh - 1;
                if (ih < 0 || ih > 6) continue;
                #pragma unroll
                for (int kw = 0; kw < 3; kw++) {
                    int iw = ow + kw - 1;
                    if (iw < 0 || iw > 6) continue;
                    int q = ih*7 + iw, tap = kh*3 + kw;
                    a += __ldg(&g_EW[(sidx[q]      + tap)*128 + co])
                       + __ldg(&g_EW[(sidx[HW + q] + tap)*128 + co])
                       + __ldg(&g_EW[(sidx[2*HW+q] + tap)*128 + co]);
                }
            }
            op[(oh*7 + ow)*NC + co] = a;
            s += a; s2 = fmaf(a, a, s2);
        }
    }
    atomicAdd(&g_bn1_sum[co], s);
    atomicAdd(&g_bn1_sq[co], s2);
}

// ---------------- conv2: shifted-accumulator FFMA2, zero shuffles --------
// Even pairs:  (o0,o1)(o2,o3)(o4,o5)(o6,j)   <- kw=0 (E0..E3), kw=2 (E1,E2,E3,P8)
// Shift pairs: (j,o0)(o1,o2)(o3,o4)(o5,o6)   <- kw=1 (E0..E3)
__global__ __launch_bounds__(128) void k_conv2(
        const float* __restrict__ bias,
        const float* __restrict__ bng, const float* __restrict__ bnb) {
    extern __shared__ float P[];                 // 128*108 floats
    int n  = blockIdx.x;
    int co = threadIdx.x;

    const float invN = 1.f / 200704.f;
    float m  = g_bn1_sum[co] * invN;
    float va = g_bn1_sq[co] * invN - m*m;
    float sc = bng[co] * rsqrtf(va + 1e-5f);
    float sh = bnb[co] - m * sc;

    #pragma unroll
    for (int q = 0; q < 108; q++) P[co*108 + q] = 0.f;
    const float* inp = g_X1 + (size_t)n * HW * NC;
    #pragma unroll 7
    for (int pos = 0; pos < HW; pos++) {
        float v = fmaxf(fmaf(inp[pos*NC + co], sc, sh), 0.f);
        int h = pos / 7, wv = pos % 7;
        P[co*108 + (h+1)*12 + (wv+1)] = v;
    }
    __syncthreads();

    unsigned pbase = smem_u32(P);
    float bv = bias[co];
    ull bp = packf2(bv, bv);
    ull accE[7][4], accS[7][4];
    #pragma unroll
    for (int oh = 0; oh < 7; oh++) {
        #pragma unroll
        for (int j = 0; j < 4; j++) { accE[oh][j] = bp; accS[oh][j] = 0ull; }
    }

    for (int ci = 0; ci < NC; ci++) {
        ull wp[9];
        #pragma unroll
        for (int tap = 0; tap < 9; tap++)
            wp[tap] = g_wdup[(tap*NC + ci)*NC + co];
        unsigned rb = pbase + ci*432;
        #pragma unroll
        for (int r = 0; r < 9; r++) {
            ull E0, E1, E2, E3, P8;
            unsigned a0 = rb + r*48;
            asm volatile("ld.shared.v2.b64 {%0,%1},[%2];" : "=l"(E0), "=l"(E1) : "r"(a0));
            asm volatile("ld.shared.v2.b64 {%0,%1},[%2];" : "=l"(E2), "=l"(E3) : "r"(a0 + 16));
            asm volatile("ld.shared.b64 %0,[%1];" : "=l"(P8) : "r"(a0 + 32));
            #pragma unroll
            for (int kh = 0; kh < 3; kh++) {
                int oh = r - kh;
                if (oh < 0 || oh > 6) continue;
                ull w0 = wp[kh*3+0], w1_ = wp[kh*3+1], w2_ = wp[kh*3+2];
                FFMA2(accE[oh][0], E0, w0);  FFMA2(accE[oh][1], E1, w0);
                FFMA2(accE[oh][2], E2, w0);  FFMA2(accE[oh][3], E3, w0);
                FFMA2(accS[oh][0], E0, w1_); FFMA2(accS[oh][1], E1, w1_);
                FFMA2(accS[oh][2], E2, w1_); FFMA2(accS[oh][3], E3, w1_);
                FFMA2(accE[oh][0], E1, w2_); FFMA2(accE[oh][1], E2, w2_);
                FFMA2(accE[oh][2], E3, w2_); FFMA2(accE[oh][3], P8, w2_);
            }
        }
    }

    float s = 0.f, s2 = 0.f;
    float mx = -3.4e38f, mn = 3.4e38f;
    #pragma unroll
    for (int oh = 0; oh < 7; oh++) {
        float e0l,e0h,e1l,e1h,e2l,e2h,e3l,e3h;
        float s0l,s0h,s1l,s1h,s2l,s2h,s3l,s3h;
        unpackf2(accE[oh][0], e0l, e0h);
        unpackf2(accE[oh][1], e1l, e1h);
        unpackf2(accE[oh][2], e2l, e2h);
        unpackf2(accE[oh][3], e3l, e3h);
        unpackf2(accS[oh][0], s0l, s0h);
        unpackf2(accS[oh][1], s1l, s1h);
        unpackf2(accS[oh][2], s2l, s2h);
        unpackf2(accS[oh][3], s3l, s3h);
        float v[7];
        v[0] = e0l + s0h;  v[1] = e0h + s1l;  v[2] = e1l + s1h;
        v[3] = e1h + s2l;  v[4] = e2l + s2h;  v[5] = e2h + s3l;
        v[6] = e3l + s3h;
        #pragma unroll
        for (int ow = 0; ow < 7; ow++) {
            float x = v[ow];
            s += x; s2 = fmaf(x, x, s2);
            mx = fmaxf(mx, x); mn = fminf(mn, x);
        }
    }
    g_cmax[n*NC + co] = mx;
    g_cmin[n*NC + co] = mn;
    atomicAdd(&g_bn2_sum[co], s);
    atomicAdd(&g_bn2_sq[co], s2);
}

// ---------------- init ----------------
__global__ void k_init_a(const float* __restrict__ codebook) {
    int i = blockIdx.x * blockDim.x + threadIdx.x;
    if (i < NS*NK*NE) { g_cb[i] = codebook[i]; g_ea[i] = codebook[i]; }
}
__global__ void k_init_b() {
    int i = blockIdx.x * blockDim.x + threadIdx.x;
    if (i < NS*NK) { g_csA[i] = 0.f; g_csB[i] = 0.f; }
    if (i < NB*64) g_h[i] = 0.f;
    if (i == 0) { g_decl = 0.0; g_el = 0.0; g_bar_cnt = 0u; g_bar_gen = 0u; }
}
__global__ void k_init_cde() {
    int i = blockIdx.x * blockDim.x + threadIdx.x;
    if (i < NK) { g_cntA[i] = 0.f; g_cntB[i] = 0.f; }
    if (i < NK*NE) { g_sumA[i] = 0.f; g_sumB[i] = 0.f; }
}

// ---------------- bn2 + maxpool + relu -> obs_feat ----------------
__global__ void k_bn2max(const float* __restrict__ bng, const float* __restrict__ bnb) {
    int i = blockIdx.x * blockDim.x + threadIdx.x;
    if (i >= NIMG*NC) return;
    int c = i & 127;
    const float invN = 1.f / 200704.f;
    float m  = g_bn2_sum[c] * invN;
    float va = g_bn2_sq[c] * invN - m*m;
    float sc = bng[c] * rsqrtf(va + 1e-5f);
    float sh = bnb[c] - m * sc;
    float raw = (sc >= 0.f) ? g_cmax[i] : g_cmin[i];
    g_obs_feat[i] = fmaxf(fmaf(raw, sc, sh), 0.f);
}

// ---------------- gi = obs_feat @ Wih^T + bih ----------------
__global__ __launch_bounds__(192) void k_gi(const float* __restrict__ wih,
                                            const float* __restrict__ bih) {
    int n0 = blockIdx.x * 8;
    int j = threadIdx.x;
    __shared__ float xs[8*128];
    for (int i = j; i < 1024; i += 192) xs[i] = g_obs_feat[n0*128 + i];
    __syncthreads();
    float acc[8];
    float bv = bih[j];
    #pragma unroll
    for (int r = 0; r < 8; r++) acc[r] = bv;
    for (int i = 0; i < 128; i++) {
        float wv = wih[j*128 + i];
        #pragma unroll
        for (int r = 0; r < 8; r++) acc[r] = fmaf(xs[r*128 + i], wv, acc[r]);
    }
    #pragma unroll
    for (int r = 0; r < 8; r++) g_gi[(n0 + r)*192 + j] = acc[r];
}

// ---------------- GRU step 0 (h=0) + z(0) ----------------
__global__ __launch_bounds__(256) void k_gruz0(const float* __restrict__ bhh,
        const float* __restrict__ prew, const float* __restrict__ preb) {
    int b = blockIdx.x, tid = threadIdx.x;
    __shared__ float gh[192], hn[64];
    if (tid < 192) gh[tid] = bhh[tid];
    __syncthreads();
    if (tid < 64) {
        const float* gi = g_gi + (size_t)(b*64)*192;
        float zz = 1.f / (1.f + expf(-(gi[64 + tid] + gh[64 + tid])));
        float r  = 1.f / (1.f + expf(-(gi[tid] + gh[tid])));
        float nn = tanhf(gi[128 + tid] + r * gh[128 + tid]);
        float h = (1.f - zz) * nn;
        hn[tid] = h; g_h[b*64 + tid] = h;
    }
    __syncthreads();
    #pragma unroll
    for (int rep = 0; rep < 2; rep++) {
        int j = tid + rep*256;
        float a = preb[j];
        for (int i = 0; i < 64; i++) a = fmaf(hn[i], prew[i*512 + j], a);
        g_z[b*512 + j] = a;
    }
}

// ---------------- grid barrier (64 blocks, single wave guaranteed) --------
__device__ __forceinline__ void grid_barrier(unsigned &gen) {
    __syncthreads();
    if (threadIdx.x == 0) {
        __threadfence();
        unsigned arrived = atomicAdd(&g_bar_cnt, 1u);
        if (arrived == 63u) {
            atomicExch(&g_bar_cnt, 0u);
            __threadfence();
            atomicExch(&g_bar_gen, gen + 1u);
        } else {
            while (atomicAdd(&g_bar_gen, 0u) < gen + 1u) { __nanosleep(64); }
        }
        __threadfence();
    }
    gen++;
    __syncthreads();
}

// ---------------- persistent scan: 63 steps, 2 phases/step ----------------
__global__ __launch_bounds__(256) void k_scan(
        const float* __restrict__ m1w, const float* __restrict__ m1b,
        const float* __restrict__ m2w, const float* __restrict__ m2b,
        const float* __restrict__ whh, const float* __restrict__ bhh,
        const float* __restrict__ prew, const float* __restrict__ preb) {
    __shared__ float cbs[64*64];
    __shared__ float zsh[64*65];
    __shared__ float red[256];
    __shared__ float invc[64];
    __shared__ float pdl[4*64];
    __shared__ int   pil[4*64];
    __shared__ int   kmin[8];
    __shared__ float dmin[8];
    __shared__ float zq[512], h1[128], hs[64], gh[192], hn[64];

    unsigned gen = 0;
    int tid = threadIdx.x;

    for (int t = 0; t < NT; t++) {
        // ================= phase A: bid = (s, kc) =================
        {
            int s = blockIdx.x >> 3, kc = blockIdx.x & 7;
            const float* csr  = (t & 1) ? g_csB : g_csA;
            float*       csw  = (t & 1) ? g_csA : g_csB;
            const float* cntp = (t & 1) ? g_cntA : g_cntB;
            const float* sump = (t & 1) ? g_sumA : g_sumB;
            float*       cntc = (t & 1) ? g_cntB : g_cntA;
            float*       sumc = (t & 1) ? g_sumB : g_sumA;

            if (tid < 8) __stcg(&cntc[blockIdx.x*8 + tid], 0.f);
            if (tid < 128) __stcg(&reinterpret_cast<float4*>(sumc + blockIdx.x*512)[tid],
                                  make_float4(0.f,0.f,0.f,0.f));

            #pragma unroll
            for (int rep = 0; rep < 16; rep++) {
                int j = tid + rep*256;
                int bb = j >> 6, e = j & 63;
                zsh[e*65 + bb] = __ldcg(&g_z[bb*512 + s*64 + e]);
            }

            if (t > 0) {
                float c1 = fmaf(0.01f, __ldcg(&cntp[tid]),       __ldcg(&csr[s*NK + tid])       * 0.99f);
                float c2 = fmaf(0.01f, __ldcg(&cntp[tid + 256]), __ldcg(&csr[s*NK + tid + 256]) * 0.99f);
                red[tid] = c1 + c2;
                __syncthreads();
                for (int off = 128; off > 0; off >>= 1) {
                    if (tid < off) red[tid] += red[tid + off];
                    __syncthreads();
                }
                float ntot = red[0];
                if (tid < 64) {
                    int k = kc*64 + tid;
                    float cs_new = fmaf(0.01f, __ldcg(&cntp[k]), __ldcg(&csr[s*NK + k]) * 0.99f);
                    __stcg(&csw[s*NK + k], cs_new);
                    float csn = (cs_new + 1e-5f) / (ntot + 512.f * 1e-5f) * ntot;
                    invc[tid] = 1.f / csn;
                }
                __syncthreads();
                float4* ea4  = reinterpret_cast<float4*>(g_ea + ((size_t)s*NK + kc*64)*NE);
                float4* cbg4 = reinterpret_cast<float4*>(g_cb + ((size_t)s*NK + kc*64)*NE);
                const float4* sm4 = reinterpret_cast<const float4*>(sump + kc*64*NE);
                float4* cbs4 = reinterpret_cast<float4*>(cbs);
                #pragma unroll
                for (int rep = 0; rep < 4; rep++) {
                    int j = tid + rep*256;
                    float inv = invc[j >> 4];
                    float4 e = ea4[j];            // block-private
                    float4 sv = __ldcg(&sm4[j]);
                    e.x = fmaf(0.01f, sv.x, e.x*0.99f);
                    e.y = fmaf(0.01f, sv.y, e.y*0.99f);
                    e.z = fmaf(0.01f, sv.z, e.z*0.99f);
                    e.w = fmaf(0.01f, sv.w, e.w*0.99f);
                    ea4[j] = e;
                    float4 cv = make_float4(e.x*inv, e.y*inv, e.z*inv, e.w*inv);
                    __stcg(&cbg4[j], cv);
                    cbs4[j] = cv;
                }
            } else {
                const float4* cbg4 = reinterpret_cast<const float4*>(g_cb + ((size_t)s*NK + kc*64)*NE);
                float4* cbs4 = reinterpret_cast<float4*>(cbs);
                #pragma unroll
                for (int rep = 0; rep < 4; rep++) cbs4[tid + rep*256] = __ldcg(&cbg4[tid + rep*256]);
            }
            __syncthreads();

            int b  = tid & 63;
            int kg = tid >> 6;
            float zreg[64];
            #pragma unroll
            for (int e = 0; e < 64; e++) zreg[e] = zsh[e*65 + b];
            float best = 3.4e38f; int bk = 0;
            #pragma unroll 4
            for (int j = 0; j < 16; j++) {
                int kl = kg*16 + j;
                const float4* row = reinterpret_cast<const float4*>(cbs + kl*64);
                float d = 0.f;
                #pragma unroll
                for (int e4 = 0; e4 < 16; e4++) {
                    float4 c = row[e4];
                    float dx = zreg[4*e4]   - c.x; d = fmaf(dx, dx, d);
                    dx = zreg[4*e4+1] - c.y; d = fmaf(dx, dx, d);
                    dx = zreg[4*e4+2] - c.z; d = fmaf(dx, dx, d);
                    dx = zreg[4*e4+3] - c.w; d = fmaf(dx, dx, d);
                }
                if (d < best) { best = d; bk = kl; }
            }
            pdl[kg*64 + b] = best; pil[kg*64 + b] = bk;
            __syncthreads();
            if (tid < 64) {
                float bd = pdl[tid]; int bi = pil[tid];
                #pragma unroll
                for (int g = 1; g < 4; g++) {
                    float d2 = pdl[g*64 + tid];
                    if (d2 < bd) { bd = d2; bi = pil[g*64 + tid]; }
                }
                __stcg(&g_pd[blockIdx.x*64 + tid], bd);
                __stcg(&g_pi[blockIdx.x*64 + tid], kc*64 + bi);
            }
        }
        grid_barrier(gen);

        // ================= phase B: bid = b =================
        {
            int b = blockIdx.x;
            float* cntc = (t & 1) ? g_cntB : g_cntA;
            float* sumc = (t & 1) ? g_sumB : g_sumA;

            if (tid < 64) hs[tid] = g_h[b*64 + tid];
            if (tid < 8) {
                int s = tid;
                float bd = 3.4e38f; int bi = 0;
                #pragma unroll
                for (int kc = 0; kc < 8; kc++) {
                    float d = __ldcg(&g_pd[(s*8 + kc)*64 + b]);
                    if (d < bd) { bd = d; bi = __ldcg(&g_pi[(s*8 + kc)*64 + b]); }
                }
                kmin[s] = bi; dmin[s] = bd;
                atomicAdd(&cntc[bi], 1.0f);
            }
            __syncthreads();
            if (tid == 0) {
                double e = 0.0;
                #pragma unroll
                for (int s = 0; s < 8; s++) e += (double)dmin[s];
                atomicAdd(&g_el, e * (1.0 / 32768.0));
            }
            #pragma unroll
            for (int rep = 0; rep < 2; rep++) {
                int j = tid + rep*256;
                int s = j >> 6, e = j & 63;
                int k = kmin[s];
                zq[j] = __ldcg(&g_cb[((size_t)s*NK + k)*NE + e]);
                atomicAdd(&sumc[k*64 + e], __ldcg(&g_z[b*512 + j]));
            }
            __syncthreads();
            if (tid < 128) {
                float a = m1b[tid];
                for (int i = 0; i < 512; i += 4) {
                    float4 zv = *reinterpret_cast<const float4*>(&zq[i]);
                    a = fmaf(zv.x, m1w[i*128 + tid], a);
                    a = fmaf(zv.y, m1w[(i+1)*128 + tid], a);
                    a = fmaf(zv.z, m1w[(i+2)*128 + tid], a);
                    a = fmaf(zv.w, m1w[(i+3)*128 + tid], a);
                }
                h1[tid] = fmaxf(a, 0.f);
            }
            __syncthreads();
            {
                float a = m2b[tid];
                for (int i = 0; i < 128; i++) a = fmaf(h1[i], m2w[i*256 + tid], a);
                if (tid < 128) g_gab_g[((size_t)t*64 + b)*128 + tid] = 1.f + a;
                else           g_gab_b[((size_t)t*64 + b)*128 + (tid - 128)] = a;
            }
            if (t < 62) {
                __syncthreads();
                if (tid < 192) {
                    float a = bhh[tid];
                    for (int i = 0; i < 64; i++) a = fmaf(hs[i], whh[tid*64 + i], a);
                    gh[tid] = a;
                }
                __syncthreads();
                if (tid < 64) {
                    const float* gi = g_gi + ((size_t)(b*64 + t + 1))*192;
                    float r  = 1.f / (1.f + expf(-(gi[tid] + gh[tid])));
                    float zz = 1.f / (1.f + expf(-(gi[64 + tid] + gh[64 + tid])));
                    float nn = tanhf(gi[128 + tid] + r * gh[128 + tid]);
                    float h = (1.f - zz) * nn + zz * hs[tid];
                    hn[tid] = h; g_h[b*64 + tid] = h;
                }
                __syncthreads();
                #pragma unroll
                for (int rep = 0; rep < 2; rep++) {
                    int j = tid + rep*256;
                    float a = preb[j];
                    for (int i = 0; i < 64; i++) a = fmaf(hn[i], prew[i*512 + j], a);
                    __stcg(&g_z[b*512 + j], a);
                }
            }
        }
        grid_barrier(gen);
    }
}

// ---------------- batched decoder, 16 rows/block ----------------
__global__ __launch_bounds__(128) void k_dec(const int* __restrict__ acts,
        const float* __restrict__ w1, const float* __restrict__ b1,
        const float* __restrict__ w2, const float* __restrict__ b2,
        const float* __restrict__ w3, const float* __restrict__ b3) {
    int row0 = blockIdx.x * 16;
    int tp = row0 >> 6;
    int b0 = row0 & 63;
    float sq = sqrtf((float)(127*127 - 8*tp));
    int t = (int)((127.0f - sq) * 0.5f);
    while ((t+1)*(127-(t+1))/2 <= tp && t < 62) t++;
    while (t*(127-t)/2 > tp) t--;
    int p = t + (tp - t*(127-t)/2);
    int c = threadIdx.x;
    __shared__ float f[16][128];
    __shared__ float h1[16][128];
    __shared__ float h2[16][128];
    __shared__ float lg[16][6];
    __shared__ float ce[16];
    #pragma unroll
    for (int j = 0; j < 16; j++) {
        int b = b0 + j;
        float of = g_obs_feat[(b*64 + p)*NC + c];
        float fl = fmaf(of, g_gab_g[((size_t)t*64 + b)*128 + c],
                            g_gab_b[((size_t)t*64 + b)*128 + c]);
        f[j][c] = fmaxf(fl, 0.f);
    }
    __syncthreads();
    float acc[16];
    float bv = b1[c];
    #pragma unroll
    for (int j = 0; j < 16; j++) acc[j] = bv;
    for (int i = 0; i < 128; i += 4) {
        float wa = w1[i*128 + c], wb = w1[(i+1)*128 + c];
        float wc = w1[(i+2)*128 + c], wd = w1[(i+3)*128 + c];
        #pragma unroll
        for (int j = 0; j < 16; j++) {
            float4 fv = *reinterpret_cast<const float4*>(&f[j][i]);
            acc[j] = fmaf(fv.x, wa, fmaf(fv.y, wb, fmaf(fv.z, wc, fmaf(fv.w, wd, acc[j]))));
        }
    }
    #pragma unroll
    for (int j = 0; j < 16; j++) h1[j][c] = fmaxf(acc[j], 0.f);
    __syncthreads();
    bv = b2[c];
    #pragma unroll
    for (int j = 0; j < 16; j++) acc[j] = bv;
    for (int i = 0; i < 128; i += 4) {
        float wa = w2[i*128 + c], wb = w2[(i+1)*128 + c];
        float wc = w2[(i+2)*128 + c], wd = w2[(i+3)*128 + c];
        #pragma unroll
        for (int j = 0; j < 16; j++) {
            float4 fv = *reinterpret_cast<const float4*>(&h1[j][i]);
            acc[j] = fmaf(fv.x, wa, fmaf(fv.y, wb, fmaf(fv.z, wc, fmaf(fv.w, wd, acc[j]))));
        }
    }
    #pragma unroll
    for (int j = 0; j < 16; j++) h2[j][c] = fmaxf(acc[j], 0.f);
    __syncthreads();
    if (c < 96) {
        int j = c / 6, o = c % 6;
        float l = b3[o];
        for (int i = 0; i < 128; i++) l = fmaf(h2[j][i], w3[i*6 + o], l);
        lg[j][o] = l;
    }
    __syncthreads();
    if (c < 16) {
        int b = b0 + c;
        float m = lg[c][0];
        #pragma unroll
        for (int i = 1; i < 6; i++) m = fmaxf(m, lg[c][i]);
        float se = 0.f;
        #pragma unroll
        for (int i = 0; i < 6; i++) se += expf(lg[c][i] - m);
        float lse = m + logf(se);
        int a = acts[b*63 + p];
        ce[c] = lse - lg[c][a];
    }
    __syncthreads();
    if (c == 0) {
        double ssum = 0.0;
        #pragma unroll
        for (int j = 0; j < 16; j++) ssum += (double)ce[j];
        atomicAdd(&g_decl, ssum);
    }
}

// ---------------- finalize ----------------
__global__ void k_final(float* __restrict__ out) {
    if (threadIdx.x == 0) {
        out[0] = (float)(g_decl / 64.0);
        out[1] = (float)(g_el / 64.0);
    }
}

// ---------------- launch ----------------
extern "C" void kernel_launch(void* const* d_in, const int* in_sizes, int n_in,
                              void* d_out, int out_size) {
    const int*   obs  = (const int*)d_in[0];
    const int*   acts = (const int*)d_in[1];
    const float* emb  = (const float*)d_in[2];
    const float* c1w  = (const float*)d_in[3];
    const float* c1b  = (const float*)d_in[4];
    const float* bn1g = (const float*)d_in[5];
    const float* bn1b = (const float*)d_in[6];
    const float* c2w  = (const float*)d_in[7];
    const float* c2b  = (const float*)d_in[8];
    const float* bn2g = (const float*)d_in[9];
    const float* bn2b = (const float*)d_in[10];
    const float* wih  = (const float*)d_in[11];
    const float* whh  = (const float*)d_in[12];
    const float* bih  = (const float*)d_in[13];
    const float* bhh  = (const float*)d_in[14];
    const float* prew = (const float*)d_in[15];
    const float* preb = (const float*)d_in[16];
    const float* cbk  = (const float*)d_in[17];
    const float* m1w  = (const float*)d_in[18];
    const float* m1b  = (const float*)d_in[19];
    const float* m2w  = (const float*)d_in[20];
    const float* m2b  = (const float*)d_in[21];
    const float* d1w  = (const float*)d_in[22];
    const float* d1b  = (const float*)d_in[23];
    const float* d2w  = (const float*)d_in[24];
    const float* d2b  = (const float*)d_in[25];
    const float* d3w  = (const float*)d_in[26];
    const float* d3b  = (const float*)d_in[27];
    float* out = (float*)d_out;

    cudaFuncSetAttribute(k_conv2, cudaFuncAttributeMaxDynamicSharedMemorySize, CONV_SMEM);

    k_wdup<<<576, 256>>>(c2w);                                   // 1: dup w2 + zero bn stats
    k_ew<<<441, 128>>>(emb, c1w);                                // 2: EW table
    k_conv1g<<<NIMG, 256>>>(obs, c1b);                           // 3: conv1 gather + bn1 stats
    k_conv2<<<NIMG, 128, CONV_SMEM>>>(c2b, bn2g, bn2b);          // 4: conv2 (ncu slot)
    k_init_a<<<1024, 256>>>(cbk);
    k_init_b<<<16, 256>>>();
    k_init_cde<<<128, 256>>>();
    k_bn2max<<<(NIMG*NC + 255)/256, 256>>>(bn2g, bn2b);
    k_gi<<<NIMG/8, 192>>>(wih, bih);
    k_gruz0<<<NB, 256>>>(bhh, prew, preb);
    k_scan<<<64, 256>>>(m1w, m1b, m2w, m2b, whh, bhh, prew, preb);
    k_dec<<<129024/16, 128>>>(acts, d1w, d1b, d2w, d2b, d3w, d3b);
    k_final<<<1, 32>>>(out);
}